// round 6
// baseline (speedup 1.0000x reference)
#include <cuda_runtime.h>
#include <math.h>

// Problem constants (fixed by dataset)
#define NSAMP 8192
#define TDIM 16
#define DDIM 64
#define GGRP 512                 // NSAMP / 16
#define NND  (NSAMP * DDIM)      // 524288 (giant row length)
#define EE   136
#define NPAIR 136                // 16*17/2 gram pairs
#define NTILE 512                // gram blocks
#define TILE_COLS 1024           // cols per gram block

// ---------------- device globals (scratch, statically allocated) ----------------
__device__ float g_partials[NTILE][NPAIR];
__device__ float g_coefQ[256];
__device__ float g_coefK[256];
__device__ float g_firstQ[16];
__device__ float g_firstK[16];
__device__ float g_uQ[64];
__device__ float g_uK[64];

__device__ __forceinline__ float wreduce(float v) {
#pragma unroll
    for (int o = 16; o; o >>= 1) v += __shfl_xor_sync(0xffffffffu, v, o);
    return v;
}

// ---------------- Kernel 1: Gram partials  G[s,s'] = sum_j H[s,j]*H[s',j] ----------------
extern "C" __global__ __launch_bounds__(256, 3)
void gram_kernel(const float* __restrict__ H) {
    extern __shared__ float gtile[];   // [16][TILE_COLS]
    const int b = blockIdx.x;
    const int tid = threadIdx.x;

    // load 16 x 1024 floats (64KB), coalesced float4
    for (int i = tid; i < 16 * (TILE_COLS / 4); i += 256) {
        int s = i >> 8;             // TILE_COLS/4 = 256 per row
        int c4 = i & 255;
        float4 v = reinterpret_cast<const float4*>(H + (size_t)s * NND + (size_t)b * TILE_COLS)[c4];
        reinterpret_cast<float4*>(gtile + s * TILE_COLS)[c4] = v;
    }
    __syncthreads();

    const int w = tid >> 5, lane = tid & 31;
    // 136 pairs = 8 warps * 17
    for (int p = w * 17; p < w * 17 + 17; ++p) {
        int s2 = 0;
        while (((s2 + 1) * (s2 + 2)) / 2 <= p) s2++;
        int s1 = p - (s2 * (s2 + 1)) / 2;
        const float* r1 = gtile + s1 * TILE_COLS;
        const float* r2 = gtile + s2 * TILE_COLS;
        float acc = 0.f;
#pragma unroll 8
        for (int c = 0; c < TILE_COLS; c += 32)
            acc = fmaf(r1[c + lane], r2[c + lane], acc);
        acc = wreduce(acc);
        if (lane == 0) g_partials[b][p] = acc;
    }
}

// ---------------- Kernel 2: finalize small algebra ----------------
extern "C" __global__ __launch_bounds__(256, 1)
void finalize_kernel(const float* __restrict__ H,
                     const float* __restrict__ wq, const float* __restrict__ wk,
                     const float* __restrict__ bq, const float* __restrict__ bk,
                     const float* __restrict__ cin) {
    __shared__ float Gf[NPAIR];
    __shared__ float h0[16];
    __shared__ float scale[16];
    __shared__ float ubv[2], bnv[2];

    const int tid = threadIdx.x;
    const float cval = cin[0];
    const float Kv = 1.f / cval;
    const float sK = sqrtf(Kv);
    const float onep = 1.f + 1e-7f;

    if (tid < NPAIR) {
        float a0 = 0.f, a1 = 0.f, a2 = 0.f, a3 = 0.f;
        for (int b = 0; b < NTILE; b += 4) {
            a0 += g_partials[b + 0][tid];
            a1 += g_partials[b + 1][tid];
            a2 += g_partials[b + 2][tid];
            a3 += g_partials[b + 3][tid];
        }
        Gf[tid] = (a0 + a1) + (a2 + a3);
    }
    if (tid >= NPAIR && tid < NPAIR + 16) h0[tid - NPAIR] = H[(size_t)(tid - NPAIR) * NND];
    __syncthreads();

    auto GX = [&](int s1, int s2) -> float {
        int a = min(s1, s2), b = max(s1, s2);
        return Gf[(b * (b + 1)) / 2 + a] - h0[s1] * h0[s2];
    };

    if (tid < 16) {
        int s = tid;
        float yn = fmaxf(sqrtf(GX(s, s)), 1e-15f);
        float th = fmaxf(h0[s] / sK, onep);
        float ar = logf(th + sqrtf(fmaxf(th * th - 1.f, 1e-7f)));
        scale[s] = sK * ar / yn;
    }
    __syncthreads();

    if (tid < 32) {
        int r = tid & 15;
        const float* W = (tid < 16) ? wq : wk;
        float* coef = (tid < 16) ? g_coefQ : g_coefK;
        float* first = (tid < 16) ? g_firstQ : g_firstK;
        float Wp[16];
#pragma unroll
        for (int s = 0; s < 16; s++) Wp[s] = W[r * 16 + s] * scale[s];
        float xn2 = 0.f;
        for (int s = 0; s < 16; s++)
            for (int s2 = 0; s2 < 16; s2++)
                xn2 = fmaf(Wp[s] * Wp[s2], GX(s, s2), xn2);
        float xn = fmaxf(sqrtf(xn2), 1e-15f);
        float th = xn / sK;
        float cA = sK * sinhf(th) / xn;
        first[r] = sK * coshf(th);
#pragma unroll
        for (int s = 0; s < 16; s++) coef[r * 16 + s] = cA * Wp[s];
    }
    if (tid == 32 || tid == 33) {
        const float* b = (tid == 32) ? bq : bk;
        float s2 = 0.f;
        for (int j = 1; j < 64; j++) s2 += b[j] * b[j];
        float bn = fmaxf(sqrtf(s2), 1e-15f);
        float tb = fmaxf(b[0] / sK, onep);
        float ub = sK * logf(tb + sqrtf(fmaxf(tb * tb - 1.f, 1e-7f)));
        ubv[tid - 32] = ub;
        bnv[tid - 32] = bn;
    }
    __syncthreads();
    if (tid < 128) {
        int j = tid & 63;
        if (tid < 64) g_uQ[j] = (j == 0) ? 0.f : ubv[0] * bq[j] / bnv[0];
        else          g_uK[j] = (j == 0) ? 0.f : ubv[1] * bk[j] / bnv[1];
    }
}

// ---------------- Kernel 3: fused main ----------------
extern "C" __global__ __launch_bounds__(256, 1)
void main_kernel(const float* __restrict__ H, const int* __restrict__ tidx,
                 const float* __restrict__ mask, const float* __restrict__ ain,
                 const float* __restrict__ cin, float* __restrict__ out) {
    extern __shared__ float smem[];
    float* tile = smem;                    // 16*1024
    float* qm   = tile + 16384;            // 16*1024
    float* km   = qm + 16384;              // 16*1024
    float* cQ   = km + 16384;              // 256
    float* cK   = cQ + 256;                // 256
    float* fQ   = cK + 256;                // 16
    float* fK   = fQ + 16;                 // 16
    float* uq   = fK + 16;                 // 64
    float* uk   = uq + 64;                 // 64
    int*   tmA  = (int*)(uk + 64);         // 136
    int*   tnA  = tmA + 136;               // 136
    float* maskS= (float*)(tnA + 136);     // 136
    float* sbuf = maskS + 136;             // 8*136
    float* ssum = sbuf + 8 * 136;          // 8*16
    float* inv0s= ssum + 128;              // 8*16
    float* lambS= inv0s + 128;             // 8*16

    const int g = blockIdx.x;
    const int tid = threadIdx.x;
    const int lane = tid & 31, warp = tid >> 5;
    const float cval = __ldg(cin);
    const float aval = __ldg(ain);
    const float Kv = 1.f / cval;
    const float sK = sqrtf(Kv);
    const float onep = 1.f + 1e-7f;

    // ---- load constants + time index ----
    if (tid < 256) { cQ[tid] = g_coefQ[tid]; cK[tid] = g_coefK[tid]; }
    if (tid < 16)  { fQ[tid] = g_firstQ[tid]; fK[tid] = g_firstK[tid]; }
    if (tid < 64)  { uq[tid] = g_uQ[tid]; uk[tid] = g_uK[tid]; }
    bool is64 = (__ldg(&tidx[1]) == 0);   // int64 buffer read as int32 -> high word 0
    if (tid < 136) {
        int tm, tn;
        if (is64) { tm = tidx[2 * tid]; tn = tidx[272 + 2 * tid]; }
        else      { tm = tidx[tid];     tn = tidx[136 + tid]; }
        tmA[tid] = tm; tnA[tid] = tn; maskS[tid] = mask[tid];
    }
    // ---- load big_h tile: samples s*512+g ----
    for (int i = tid; i < 16 * 256; i += 256) {
        int s = i >> 8, c4 = i & 255;
        float4 v = reinterpret_cast<const float4*>(H + (size_t)(s * 512 + g) * 1024)[c4];
        reinterpret_cast<float4*>(tile + s * 1024)[c4] = v;
    }
    __syncthreads();

    // ---- phase 2: 16x16 mix -> q,k raw ----
#pragma unroll
    for (int it = 0; it < 4; ++it) {
        int col = tid + it * 256;
        float tv[16];
#pragma unroll
        for (int s = 0; s < 16; s++) tv[s] = tile[s * 1024 + col];
#pragma unroll
        for (int r = 0; r < 16; r++) {
            const float4* cq4 = reinterpret_cast<const float4*>(cQ + r * 16);
            const float4* ck4 = reinterpret_cast<const float4*>(cK + r * 16);
            float aq = 0.f, ak = 0.f;
#pragma unroll
            for (int s4 = 0; s4 < 4; s4++) {
                float4 cq = cq4[s4], ck = ck4[s4];
                aq = fmaf(cq.x, tv[s4*4+0], aq); aq = fmaf(cq.y, tv[s4*4+1], aq);
                aq = fmaf(cq.z, tv[s4*4+2], aq); aq = fmaf(cq.w, tv[s4*4+3], aq);
                ak = fmaf(ck.x, tv[s4*4+0], ak); ak = fmaf(ck.y, tv[s4*4+1], ak);
                ak = fmaf(ck.z, tv[s4*4+2], ak); ak = fmaf(ck.w, tv[s4*4+3], ak);
            }
            if (g == 0 && col == 0) { aq = fQ[r]; ak = fK[r]; }  // expmap0 first column
            qm[r * 1024 + col] = aq;
            km[r * 1024 + col] = ak;
        }
    }
    __syncthreads();

    // ---- phase 3: mobius_add(b) + proj per 64-dim row (512 rows, warp per row) ----
    for (int i = 0; i < 64; i++) {
        int rr = warp * 64 + i;
        float* X = (rr < 256) ? qm : km;
        const float* U = (rr < 256) ? uq : uk;
        int rloc = rr & 255;
        int samp = rloc >> 4, ttv = rloc & 15;
        float* row = X + samp * 1024 + ttv * 64;
        float xa = row[lane], xb = row[lane + 32];
        float ua = U[lane],  ub = U[lane + 32];
        float x0 = __shfl_sync(0xffffffffu, xa, 0);
        float xam = (lane == 0) ? 0.f : xa;
        float yn2 = wreduce(xam * xam + xb * xb);
        float yn = fmaxf(sqrtf(yn2), 1e-15f);
        float du = wreduce(xam * ua + xb * ub);
        float alpha = du / (yn * sK);
        float fac = alpha * (sK - x0) / yn;
        float wa = ua - fac * xa;
        float wb = ub - fac * xb;
        float wam = (lane == 0) ? 0.f : wa;
        float ux = wreduce(xam * wam + xb * wb);
        float first = ux / fmaxf(x0, 1e-7f);
        float w2 = wreduce(wam * wam + wb * wb);
        float md = fmaxf(w2 - first * first, 1e-7f);
        float nrm = fminf(sqrtf(md), 1e6f);
        float th = fmaxf(nrm / sK, 1e-15f);
        float ch = coshf(th);
        float sh = sinhf(th) / th;
        float ra = ch * xa + sh * wa;
        float rb = ch * xb + sh * wb;
        float ram = (lane == 0) ? 0.f : ra;
        float r2 = wreduce(ram * ram + rb * rb);
        float o0 = sqrtf(fmaxf(Kv + r2, 1e-7f));
        row[lane] = (lane == 0) ? o0 : ra;
        row[lane + 32] = rb;
    }
    __syncthreads();

    // ---- phase 4: attention per sample (warp per sample, 2 rounds) ----
    for (int it = 0; it < 2; ++it) {
        int sm = warp + it * 8;
        const float* tsm = tile + sm * 1024;

        // lorenz factor + 1/x0 per tt
        for (int ttv = 0; ttv < 16; ++ttv) {
            float h0v = tsm[ttv * 64];
            float iv = 1.f / h0v;
            float va = (lane == 0) ? 0.f : tsm[ttv * 64 + lane] * iv;
            float vb = tsm[ttv * 64 + lane + 32] * iv;
            float sv = wreduce(va * va + vb * vb);
            if (lane == 0) {
                lambS[warp * 16 + ttv] = 1.f / sqrtf(1.f - fminf(sv, 0.9f));
                inv0s[warp * 16 + ttv] = iv;
            }
        }
        __syncwarp();

        // s[e] = exp(-a*sqdist - c + mask)
        const float* qs = qm + sm * 1024;
        const float* ks = km + sm * 1024;
        for (int base = 0; base < 160; base += 32) {
            int e = base + lane;
            if (e < 136) {
                int m = tmA[e], n2 = tnA[e];
                const float* qr = qs + m * 64;
                const float* kr = ks + n2 * 64;
                float acc = 0.f;
#pragma unroll
                for (int d0 = 0; d0 < 64; ++d0) {
                    int d = (d0 + lane) & 63;     // lane-rotated: conflict-free
                    acc = fmaf(qr[d], kr[d], acc);
                }
                float mdot = acc - 2.f * qr[0] * kr[0];
                float th = fmaxf(-mdot * cval, onep);
                float ar = logf(th + sqrtf(fmaxf(th * th - 1.f, 1e-7f)));
                float sq = fminf(Kv * ar * ar, 50.f);
                sbuf[warp * 136 + e] = expf(-aval * sq - cval + maskS[e]);
            }
        }
        __syncwarp();

        // s_sum per m (generic, no ordering assumption)
        if (lane < 16) {
            float acc = 0.f;
            for (int e = 0; e < 136; e++)
                if (tmA[e] == lane) acc += sbuf[warp * 136 + e];
            ssum[warp * 16 + lane] = acc;
        }
        __syncwarp();

        // coef_e = lamb[tn] * s_e / s_sum[tn]   (overwrite sbuf)
        for (int base = 0; base < 160; base += 32) {
            int e = base + lane;
            if (e < 136) {
                int tn = tnA[e];
                sbuf[warp * 136 + e] = lambS[warp * 16 + tn] * sbuf[warp * 136 + e]
                                       / ssum[warp * 16 + tn];
            }
        }
        __syncwarp();

        // z/w scatter by contiguous t_m runs, flush -> k2h -> global
        int cur = tmA[0];
        float a0 = 0.f, a1 = 0.f;  // a0: dim lane; a1: dim lane+32 (lane<31) or w_sum (lane 31)
        const size_t obase = (size_t)(sm * 512 + g) * 16 * 64;
        for (int e = 0; e <= 136; ++e) {
            int me = (e < 136) ? tmA[e] : -1;
            if (me != cur) {
                float wsum = __shfl_sync(0xffffffffu, a1, 31);
                float o0 = a0 / wsum;
                float o1 = (lane < 31) ? a1 / wsum : 0.f;
                float s2 = wreduce(o0 * o0 + o1 * o1);
                float inv = 1.f / sqrtf(1.f - fminf(s2, 0.999f));
                float* op = out + obase + (size_t)cur * 64;
                op[1 + lane] = o0 * inv;
                if (lane < 31) op[33 + lane] = o1 * inv;
                if (lane == 0) op[0] = inv;
                cur = me; a0 = 0.f; a1 = 0.f;
                if (e == 136) break;
            }
            float ce = sbuf[warp * 136 + e];
            int tn = tnA[e];
            float civ = ce * inv0s[warp * 16 + tn];
            const float* hr = tsm + tn * 64;
            a0 = fmaf(civ, hr[1 + lane], a0);
            a1 = (lane < 31) ? fmaf(civ, hr[33 + lane], a1) : (a1 + ce);
        }
    }
}

// ---------------- launch ----------------
extern "C" void kernel_launch(void* const* d_in, const int* in_sizes, int n_in,
                              void* d_out, int out_size) {
    (void)in_sizes; (void)n_in; (void)out_size;
    const float* H    = (const float*)d_in[0];
    const int*   tidx = (const int*)d_in[1];
    const float* mask = (const float*)d_in[2];
    const float* wq   = (const float*)d_in[3];
    const float* wk   = (const float*)d_in[4];
    const float* bq   = (const float*)d_in[5];
    const float* bk   = (const float*)d_in[6];
    const float* a    = (const float*)d_in[7];
    const float* c    = (const float*)d_in[8];
    float* out = (float*)d_out;

    const int GRAM_SMEM = 16 * TILE_COLS * 4;              // 64KB
    // tile+qm+km + consts + index + per-warp buffers
    const int MAIN_FLOATS = 3 * 16384 + 256 + 256 + 16 + 16 + 64 + 64
                            + 136 + 136 + 136 + 8 * 136 + 128 + 128 + 128;
    const int MAIN_SMEM = MAIN_FLOATS * 4;                 // ~207KB

    cudaFuncSetAttribute(gram_kernel, cudaFuncAttributeMaxDynamicSharedMemorySize, GRAM_SMEM);
    cudaFuncSetAttribute(main_kernel, cudaFuncAttributeMaxDynamicSharedMemorySize, MAIN_SMEM);

    gram_kernel<<<NTILE, 256, GRAM_SMEM>>>(H);
    finalize_kernel<<<1, 256>>>(H, wq, wk, bq, bk, c);
    main_kernel<<<GGRP, 256, MAIN_SMEM>>>(H, tidx, mask, a, c, out);
}

// round 7
// speedup vs baseline: 1.5976x; 1.5976x over previous
#include <cuda_runtime.h>
#include <math.h>

// Problem constants (fixed by dataset)
#define NSAMP 8192
#define NND  (NSAMP * 64)        // 524288 (giant row length)
#define NPAIR 136                // 16*17/2 gram pairs
#define GTILE_COLS 256           // cols per gram block
#define GNTILE 2048              // 524288 / 256

// ---------------- device globals (scratch, statically allocated) ----------------
__device__ float g_partials[NPAIR][GNTILE];
__device__ float g_coefQ[256];
__device__ float g_coefK[256];
__device__ float g_firstQ[16];
__device__ float g_firstK[16];
__device__ float g_uQ[64];
__device__ float g_uK[64];

typedef unsigned long long ull;

__device__ __forceinline__ float wreduce(float v) {
#pragma unroll
    for (int o = 16; o; o >>= 1) v += __shfl_xor_sync(0xffffffffu, v, o);
    return v;
}

__device__ __forceinline__ ull fma2(ull a, ull b, ull c) {
    ull d; asm("fma.rn.f32x2 %0, %1, %2, %3;" : "=l"(d) : "l"(a), "l"(b), "l"(c));
    return d;
}
__device__ __forceinline__ ull pack2(float lo, float hi) {
    ull d; asm("mov.b64 %0, {%1, %2};" : "=l"(d) : "f"(lo), "f"(hi));
    return d;
}
__device__ __forceinline__ void unpack2(ull v, float& lo, float& hi) {
    asm("mov.b64 {%0, %1}, %2;" : "=f"(lo), "=f"(hi) : "l"(v));
}

// ---------------- Kernel 1: Gram partials, 4x4 pair-block register tiling ----------------
extern "C" __global__ __launch_bounds__(256)
void gram_kernel(const float* __restrict__ H) {
    __shared__ float gt[16 * GTILE_COLS];   // 16KB
    const int b = blockIdx.x;
    const int tid = threadIdx.x;

    // load 16 x 256 floats (16KB), coalesced float4
    for (int i = tid; i < 16 * (GTILE_COLS / 4); i += 256) {
        int s = i >> 6;                 // 64 float4 per row
        int c4 = i & 63;
        float4 v = reinterpret_cast<const float4*>(H + (size_t)s * NND + (size_t)b * GTILE_COLS)[c4];
        reinterpret_cast<float4*>(gt + s * GTILE_COLS)[c4] = v;
    }
    __syncthreads();

    const int w = tid >> 5, lane = tid & 31;
    // 10 4x4 blocks covering the 16x16 lower triangle
    const int bi_arr[10] = {0, 1, 1, 2, 2, 2, 3, 3, 3, 3};
    const int bj_arr[10] = {0, 0, 1, 0, 1, 2, 0, 1, 2, 3};

    for (int blk = w; blk < 10; blk += 8) {
        int bi = bi_arr[blk], bj = bj_arr[blk];
        const float* A  = gt + (bi * 4) * GTILE_COLS + lane;
        const float* Bp = gt + (bj * 4) * GTILE_COLS + lane;
        float acc[16];
#pragma unroll
        for (int i = 0; i < 16; i++) acc[i] = 0.f;
#pragma unroll
        for (int c = 0; c < GTILE_COLS; c += 32) {
            float a0 = A[c], a1 = A[c + 256], a2 = A[c + 512], a3 = A[c + 768];
            float b0 = Bp[c], b1 = Bp[c + 256], b2 = Bp[c + 512], b3 = Bp[c + 768];
            acc[0]  = fmaf(a0, b0, acc[0]);   acc[1]  = fmaf(a0, b1, acc[1]);
            acc[2]  = fmaf(a0, b2, acc[2]);   acc[3]  = fmaf(a0, b3, acc[3]);
            acc[4]  = fmaf(a1, b0, acc[4]);   acc[5]  = fmaf(a1, b1, acc[5]);
            acc[6]  = fmaf(a1, b2, acc[6]);   acc[7]  = fmaf(a1, b3, acc[7]);
            acc[8]  = fmaf(a2, b0, acc[8]);   acc[9]  = fmaf(a2, b1, acc[9]);
            acc[10] = fmaf(a2, b2, acc[10]);  acc[11] = fmaf(a2, b3, acc[11]);
            acc[12] = fmaf(a3, b0, acc[12]);  acc[13] = fmaf(a3, b1, acc[13]);
            acc[14] = fmaf(a3, b2, acc[14]);  acc[15] = fmaf(a3, b3, acc[15]);
        }
#pragma unroll
        for (int ki = 0; ki < 4; ki++) {
#pragma unroll
            for (int kj = 0; kj < 4; kj++) {
                float v = wreduce(acc[ki * 4 + kj]);
                int s2 = bi * 4 + ki, s1 = bj * 4 + kj;
                if (lane == 0 && s1 <= s2)
                    g_partials[(s2 * (s2 + 1)) / 2 + s1][b] = v;
            }
        }
    }
}

// ---------------- Kernel 2: finalize small algebra ----------------
extern "C" __global__ __launch_bounds__(256, 1)
void finalize_kernel(const float* __restrict__ H,
                     const float* __restrict__ wq, const float* __restrict__ wk,
                     const float* __restrict__ bq, const float* __restrict__ bk,
                     const float* __restrict__ cin) {
    __shared__ float Gf[NPAIR];
    __shared__ float h0[16];
    __shared__ float scale[16];
    __shared__ float ubv[2], bnv[2];

    const int tid = threadIdx.x;
    const int w = tid >> 5, lane = tid & 31;
    const float cval = cin[0];
    const float Kv = 1.f / cval;
    const float sK = sqrtf(Kv);
    const float onep = 1.f + 1e-7f;

    // warp-parallel coalesced reduction of partials
    for (int p = w; p < NPAIR; p += 8) {
        float acc = 0.f;
        for (int k = lane; k < GNTILE; k += 32) acc += g_partials[p][k];
        acc = wreduce(acc);
        if (lane == 0) Gf[p] = acc;
    }
    if (tid < 16) h0[tid] = H[(size_t)tid * NND];
    __syncthreads();

    auto GX = [&](int s1, int s2) -> float {
        int a = min(s1, s2), b = max(s1, s2);
        return Gf[(b * (b + 1)) / 2 + a] - h0[s1] * h0[s2];
    };

    if (tid < 16) {
        int s = tid;
        float yn = fmaxf(sqrtf(GX(s, s)), 1e-15f);
        float th = fmaxf(h0[s] / sK, onep);
        float ar = logf(th + sqrtf(fmaxf(th * th - 1.f, 1e-7f)));
        scale[s] = sK * ar / yn;
    }
    __syncthreads();

    if (tid < 32) {
        int r = tid & 15;
        const float* W = (tid < 16) ? wq : wk;
        float* coef = (tid < 16) ? g_coefQ : g_coefK;
        float* first = (tid < 16) ? g_firstQ : g_firstK;
        float Wp[16];
#pragma unroll
        for (int s = 0; s < 16; s++) Wp[s] = W[r * 16 + s] * scale[s];
        float xn2 = 0.f;
        for (int s = 0; s < 16; s++)
            for (int s2 = 0; s2 < 16; s2++)
                xn2 = fmaf(Wp[s] * Wp[s2], GX(s, s2), xn2);
        float xn = fmaxf(sqrtf(xn2), 1e-15f);
        float th = xn / sK;
        float cA = sK * sinhf(th) / xn;
        first[r] = sK * coshf(th);
#pragma unroll
        for (int s = 0; s < 16; s++) coef[r * 16 + s] = cA * Wp[s];
    }
    if (tid == 32 || tid == 33) {
        const float* b = (tid == 32) ? bq : bk;
        float s2 = 0.f;
        for (int j = 1; j < 64; j++) s2 += b[j] * b[j];
        float bn = fmaxf(sqrtf(s2), 1e-15f);
        float tb = fmaxf(b[0] / sK, onep);
        float ub = sK * logf(tb + sqrtf(fmaxf(tb * tb - 1.f, 1e-7f)));
        ubv[tid - 32] = ub;
        bnv[tid - 32] = bn;
    }
    __syncthreads();
    if (tid < 128) {
        int j = tid & 63;
        if (tid < 64) g_uQ[j] = (j == 0) ? 0.f : ubv[0] * bq[j] / bnv[0];
        else          g_uK[j] = (j == 0) ? 0.f : ubv[1] * bk[j] / bnv[1];
    }
}

// ---------------- Kernel 3: fused main, 512 threads ----------------
extern "C" __global__ __launch_bounds__(512, 1)
void main_kernel(const float* __restrict__ H, const int* __restrict__ tidx,
                 const float* __restrict__ mask, const float* __restrict__ ain,
                 const float* __restrict__ cin, float* __restrict__ out) {
    extern __shared__ float smem[];
    float* tile = smem;                    // 16*1024
    float* qm   = tile + 16384;            // 16*1024
    float* km   = qm + 16384;              // 16*1024
    float* cQ   = km + 16384;              // 256
    float* cK   = cQ + 256;                // 256
    float* fQ   = cK + 256;                // 16
    float* fK   = fQ + 16;                 // 16
    float* uq   = fK + 16;                 // 64
    float* uk   = uq + 64;                 // 64
    int*   tmA  = (int*)(uk + 64);         // 136
    int*   tnA  = tmA + 136;               // 136
    float* maskS= (float*)(tnA + 136);     // 136
    float* sbuf = maskS + 136;             // 16*136
    float* ssum = sbuf + 16 * 136;         // 16*16
    float* inv0s= ssum + 256;              // 16*16
    float* lambS= inv0s + 256;             // 16*16

    const int g = blockIdx.x;
    const int tid = threadIdx.x;
    const int lane = tid & 31, warp = tid >> 5;
    const float cval = __ldg(cin);
    const float aval = __ldg(ain);
    const float Kv = 1.f / cval;
    const float sK = sqrtf(Kv);
    const float onep = 1.f + 1e-7f;

    // ---- load constants + time index ----
    if (tid < 256) { cQ[tid] = g_coefQ[tid]; cK[tid] = g_coefK[tid]; }
    if (tid < 16)  { fQ[tid] = g_firstQ[tid]; fK[tid] = g_firstK[tid]; }
    if (tid < 64)  { uq[tid] = g_uQ[tid]; uk[tid] = g_uK[tid]; }
    bool is64 = (__ldg(&tidx[1]) == 0);   // int64 buffer read as int32 -> high word 0
    if (tid < 136) {
        int tm, tn;
        if (is64) { tm = tidx[2 * tid]; tn = tidx[272 + 2 * tid]; }
        else      { tm = tidx[tid];     tn = tidx[136 + tid]; }
        tmA[tid] = tm; tnA[tid] = tn; maskS[tid] = mask[tid];
    }
    // ---- load big_h tile: samples s*512+g ----
    for (int i = tid; i < 16 * 256; i += 512) {
        int s = i >> 8, c4 = i & 255;
        float4 v = reinterpret_cast<const float4*>(H + (size_t)(s * 512 + g) * 1024)[c4];
        reinterpret_cast<float4*>(tile + s * 1024)[c4] = v;
    }
    __syncthreads();

    // ---- phase 2: 16x16 mix -> q,k raw (packed f32x2) ----
    {
        const float2* t2 = reinterpret_cast<const float2*>(tile);
        float2* q2 = reinterpret_cast<float2*>(qm);
        float2* k2 = reinterpret_cast<float2*>(km);
        ull tv[16];
#pragma unroll
        for (int s = 0; s < 16; s++) {
            float2 v = t2[s * 512 + tid];
            tv[s] = pack2(v.x, v.y);
        }
#pragma unroll
        for (int r = 0; r < 16; r++) {
            const float4* cq4 = reinterpret_cast<const float4*>(cQ + r * 16);
            const float4* ck4 = reinterpret_cast<const float4*>(cK + r * 16);
            ull aq = 0ull, ak = 0ull;
#pragma unroll
            for (int s4 = 0; s4 < 4; s4++) {
                float4 cq = cq4[s4], ck = ck4[s4];
                aq = fma2(pack2(cq.x, cq.x), tv[s4 * 4 + 0], aq);
                aq = fma2(pack2(cq.y, cq.y), tv[s4 * 4 + 1], aq);
                aq = fma2(pack2(cq.z, cq.z), tv[s4 * 4 + 2], aq);
                aq = fma2(pack2(cq.w, cq.w), tv[s4 * 4 + 3], aq);
                ak = fma2(pack2(ck.x, ck.x), tv[s4 * 4 + 0], ak);
                ak = fma2(pack2(ck.y, ck.y), tv[s4 * 4 + 1], ak);
                ak = fma2(pack2(ck.z, ck.z), tv[s4 * 4 + 2], ak);
                ak = fma2(pack2(ck.w, ck.w), tv[s4 * 4 + 3], ak);
            }
            float qlo, qhi, klo, khi;
            unpack2(aq, qlo, qhi);
            unpack2(ak, klo, khi);
            if (g == 0 && tid == 0) { qlo = fQ[r]; klo = fK[r]; }  // expmap0 first column
            q2[r * 512 + tid] = make_float2(qlo, qhi);
            k2[r * 512 + tid] = make_float2(klo, khi);
        }
    }
    __syncthreads();

    // ---- phase 3: mobius_add(b) + proj, thread-per-row (512 rows), no shuffles ----
    {
        float* X = (tid < 256) ? qm : km;
        const float* U = (tid < 256) ? uq : uk;
        int rloc = tid & 255;
        float* row = X + (rloc >> 4) * 1024 + (rloc & 15) * 64;
        const int j0 = (64 - lane) & 63;    // register index whose dim is 0

        float x[64];
        float yn2 = 0.f, du = 0.f, x0 = 0.f;
#pragma unroll
        for (int j = 0; j < 64; j++) {
            int d = (j + lane) & 63;
            float xv = row[d];
            if (j == j0) { x0 = xv; xv = 0.f; }  // zero dim0 in register copy
            x[j] = xv;
            yn2 = fmaf(xv, xv, yn2);
            du  = fmaf(xv, U[d], du);
        }
        float yn = fmaxf(sqrtf(fmaxf(yn2, 0.f)), 1e-15f);
        float alpha = du / (yn * sK);
        float fac = alpha * (sK - x0) / yn;

        float ux = 0.f, w2 = 0.f;
#pragma unroll
        for (int j = 0; j < 64; j++) {
            int d = (j + lane) & 63;
            float wv = fmaf(-fac, x[j], U[d]);      // x[j0]=0, U[0]=0 -> wv(dim0)=0
            ux = fmaf(x[j], wv, ux);
            w2 = fmaf(wv, wv, w2);
        }
        float first = ux / fmaxf(x0, 1e-7f);
        float md = fmaxf(w2 - first * first, 1e-7f);
        float nrm = fminf(sqrtf(md), 1e6f);
        float th = fmaxf(nrm / sK, 1e-15f);
        float ch = coshf(th);
        float shn = sinhf(th) / th;

        float r2 = 0.f;
#pragma unroll
        for (int j = 0; j < 64; j++) {
            int d = (j + lane) & 63;
            float wv = fmaf(-fac, x[j], U[d]);
            float rv = fmaf(ch, x[j], shn * wv);
            row[d] = rv;
            r2 = fmaf(rv, rv, r2);
        }
        float o0 = sqrtf(fmaxf(Kv + r2, 1e-7f));
        row[0] = o0;    // overwrite dim0 (32-way conflicted single store, once)
    }
    __syncthreads();

    // ---- phase 4: attention, warp per sample (16 warps, 1 round) ----
    {
        const int sm = warp;
        const float* tsm = tile + sm * 1024;

        // lorenz factor + 1/x0, lanes 0..15 (lane = tt), rotated conflict-free
        if (lane < 16) {
            int ttv = lane;
            const float* bp = tsm + ttv * 64;
            float h0v = bp[0];
            float iv = 1.f / h0v;
            float sv = 0.f;
#pragma unroll
            for (int d0 = 0; d0 < 64; d0++) {
                int d = (d0 + ttv) & 63;
                float v = bp[d] * iv;
                if (d != 0) sv = fmaf(v, v, sv);
            }
            lambS[sm * 16 + ttv] = 1.f / sqrtf(1.f - fminf(sv, 0.9f));
            inv0s[sm * 16 + ttv] = iv;
        }
        __syncwarp();

        // s[e] = exp(-a*sqdist - c + mask)
        const float* qs = qm + sm * 1024;
        const float* ks = km + sm * 1024;
        for (int base = 0; base < 160; base += 32) {
            int e = base + lane;
            if (e < 136) {
                int m = tmA[e], n2 = tnA[e];
                const float* qr = qs + m * 64;
                const float* kr = ks + n2 * 64;
                float acc = 0.f;
#pragma unroll
                for (int d0 = 0; d0 < 64; ++d0) {
                    int d = (d0 + lane) & 63;     // lane-rotated: conflict-free
                    acc = fmaf(qr[d], kr[d], acc);
                }
                float mdot = acc - 2.f * qr[0] * kr[0];
                float th = fmaxf(-mdot * cval, onep);
                float ar = logf(th + sqrtf(fmaxf(th * th - 1.f, 1e-7f)));
                float sq = fminf(Kv * ar * ar, 50.f);
                sbuf[sm * 136 + e] = expf(-aval * sq - cval + maskS[e]);
            }
        }
        __syncwarp();

        // s_sum per m (generic, no ordering assumption)
        if (lane < 16) {
            float acc = 0.f;
            for (int e = 0; e < 136; e++)
                if (tmA[e] == lane) acc += sbuf[sm * 136 + e];
            ssum[sm * 16 + lane] = acc;
        }
        __syncwarp();

        // coef_e = lamb[tn] * s_e / s_sum[tn]   (overwrite sbuf)
        for (int base = 0; base < 160; base += 32) {
            int e = base + lane;
            if (e < 136) {
                int tn = tnA[e];
                sbuf[sm * 136 + e] = lambS[sm * 16 + tn] * sbuf[sm * 136 + e]
                                     / ssum[sm * 16 + tn];
            }
        }
        __syncwarp();

        // z/w scatter by contiguous t_m runs, flush -> k2h -> global
        int cur = tmA[0];
        float a0 = 0.f, a1 = 0.f;  // a0: dim lane; a1: dim lane+32 (lane<31) or w_sum (lane 31)
        const size_t obase = (size_t)(sm * 512 + g) * 1024;
        for (int e = 0; e <= 136; ++e) {
            int me = (e < 136) ? tmA[e] : -1;
            if (me != cur) {
                float wsum = __shfl_sync(0xffffffffu, a1, 31);
                float o0 = a0 / wsum;
                float o1 = (lane < 31) ? a1 / wsum : 0.f;
                float s2 = wreduce(o0 * o0 + o1 * o1);
                float inv = 1.f / sqrtf(1.f - fminf(s2, 0.999f));
                float* op = out + obase + (size_t)cur * 64;
                op[1 + lane] = o0 * inv;
                if (lane < 31) op[33 + lane] = o1 * inv;
                if (lane == 0) op[0] = inv;
                cur = me; a0 = 0.f; a1 = 0.f;
                if (e == 136) break;
            }
            float ce = sbuf[sm * 136 + e];
            int tn = tnA[e];
            float civ = ce * inv0s[sm * 16 + tn];
            const float* hr = tsm + tn * 64;
            a0 = fmaf(civ, hr[1 + lane], a0);
            a1 = (lane < 31) ? fmaf(civ, hr[33 + lane], a1) : (a1 + ce);
        }
    }
}

// ---------------- launch ----------------
extern "C" void kernel_launch(void* const* d_in, const int* in_sizes, int n_in,
                              void* d_out, int out_size) {
    (void)in_sizes; (void)n_in; (void)out_size;
    const float* H    = (const float*)d_in[0];
    const int*   tidx = (const int*)d_in[1];
    const float* mask = (const float*)d_in[2];
    const float* wq   = (const float*)d_in[3];
    const float* wk   = (const float*)d_in[4];
    const float* bq   = (const float*)d_in[5];
    const float* bk   = (const float*)d_in[6];
    const float* a    = (const float*)d_in[7];
    const float* c    = (const float*)d_in[8];
    float* out = (float*)d_out;

    const int MAIN_FLOATS = 3 * 16384 + 256 + 256 + 16 + 16 + 64 + 64
                            + 136 + 136 + 136 + 16 * 136 + 256 + 256 + 256;
    const int MAIN_SMEM = MAIN_FLOATS * 4;   // ~208KB

    cudaFuncSetAttribute(main_kernel, cudaFuncAttributeMaxDynamicSharedMemorySize, MAIN_SMEM);

    gram_kernel<<<GNTILE, 256>>>(H);
    finalize_kernel<<<1, 256>>>(H, wq, wk, bq, bk, c);
    main_kernel<<<512, 512, MAIN_SMEM>>>(H, tidx, mask, a, c, out);
}

// round 8
// speedup vs baseline: 3.0169x; 1.8884x over previous
#include <cuda_runtime.h>
#include <math.h>

// Problem constants (fixed by dataset)
#define NSAMP 8192
#define NND  (NSAMP * 64)        // 524288 (giant row length)
#define NPAIR 136                // 16*17/2 gram pairs
#define GTILE_COLS 512           // cols per gram block
#define GNTILE 1024              // 524288 / 512

// ---------------- device globals (scratch, statically allocated) ----------------
__device__ float g_partials[NPAIR][GNTILE];
__device__ float g_gram[NPAIR];
__device__ float g_coefQ[256];
__device__ float g_coefK[256];
__device__ float g_firstQ[16];
__device__ float g_firstK[16];
__device__ float g_uQ[64];
__device__ float g_uK[64];

typedef unsigned long long ull;

__device__ __forceinline__ float wreduce(float v) {
#pragma unroll
    for (int o = 16; o; o >>= 1) v += __shfl_xor_sync(0xffffffffu, v, o);
    return v;
}

__device__ __forceinline__ ull fma2(ull a, ull b, ull c) {
    ull d; asm("fma.rn.f32x2 %0, %1, %2, %3;" : "=l"(d) : "l"(a), "l"(b), "l"(c));
    return d;
}
__device__ __forceinline__ ull pack2(float lo, float hi) {
    ull d; asm("mov.b64 %0, {%1, %2};" : "=l"(d) : "f"(lo), "f"(hi));
    return d;
}
__device__ __forceinline__ void unpack2(ull v, float& lo, float& hi) {
    asm("mov.b64 {%0, %1}, %2;" : "=f"(lo), "=f"(hi) : "l"(v));
}

// ---------------- Kernel 1: Gram partials, warp-per-4x4-block (10 warps) ----------------
extern "C" __global__ __launch_bounds__(320)
void gram_kernel(const float* __restrict__ H) {
    __shared__ float gt[16 * GTILE_COLS];   // 32KB
    const int b = blockIdx.x;
    const int tid = threadIdx.x;

    // load 16 x 512 floats (32KB), coalesced float4
    const float4* H4 = reinterpret_cast<const float4*>(H);
    for (int i = tid; i < 16 * (GTILE_COLS / 4); i += 320) {
        int s = i >> 7;                 // 128 float4 per row
        int c4 = i & 127;
        reinterpret_cast<float4*>(gt + s * GTILE_COLS)[c4] =
            H4[(size_t)s * (NND / 4) + (size_t)b * (GTILE_COLS / 4) + c4];
    }
    __syncthreads();

    const int w = tid >> 5, lane = tid & 31;
    // 10 4x4 blocks covering the 16x16 lower triangle; one warp each
    const int bi_arr[10] = {0, 1, 1, 2, 2, 2, 3, 3, 3, 3};
    const int bj_arr[10] = {0, 0, 1, 0, 1, 2, 0, 1, 2, 3};
    const int bi = bi_arr[w], bj = bj_arr[w];

    const float* A  = gt + (bi * 4) * GTILE_COLS + lane;
    const float* Bp = gt + (bj * 4) * GTILE_COLS + lane;
    float acc[16];
#pragma unroll
    for (int i = 0; i < 16; i++) acc[i] = 0.f;
#pragma unroll
    for (int c = 0; c < GTILE_COLS; c += 32) {
        float a0 = A[c], a1 = A[c + GTILE_COLS], a2 = A[c + 2 * GTILE_COLS], a3 = A[c + 3 * GTILE_COLS];
        float b0 = Bp[c], b1 = Bp[c + GTILE_COLS], b2 = Bp[c + 2 * GTILE_COLS], b3 = Bp[c + 3 * GTILE_COLS];
        acc[0]  = fmaf(a0, b0, acc[0]);   acc[1]  = fmaf(a0, b1, acc[1]);
        acc[2]  = fmaf(a0, b2, acc[2]);   acc[3]  = fmaf(a0, b3, acc[3]);
        acc[4]  = fmaf(a1, b0, acc[4]);   acc[5]  = fmaf(a1, b1, acc[5]);
        acc[6]  = fmaf(a1, b2, acc[6]);   acc[7]  = fmaf(a1, b3, acc[7]);
        acc[8]  = fmaf(a2, b0, acc[8]);   acc[9]  = fmaf(a2, b1, acc[9]);
        acc[10] = fmaf(a2, b2, acc[10]);  acc[11] = fmaf(a2, b3, acc[11]);
        acc[12] = fmaf(a3, b0, acc[12]);  acc[13] = fmaf(a3, b1, acc[13]);
        acc[14] = fmaf(a3, b2, acc[14]);  acc[15] = fmaf(a3, b3, acc[15]);
    }
#pragma unroll
    for (int ki = 0; ki < 4; ki++) {
#pragma unroll
        for (int kj = 0; kj < 4; kj++) {
            float v = wreduce(acc[ki * 4 + kj]);
            int s2 = bi * 4 + ki, s1 = bj * 4 + kj;
            if (lane == 0 && s1 <= s2)
                g_partials[(s2 * (s2 + 1)) / 2 + s1][b] = v;
        }
    }
}

// ---------------- Kernel 1b: parallel deterministic reduction of partials ----------------
extern "C" __global__ __launch_bounds__(256)
void reduce_kernel() {
    __shared__ float red[8];
    const int p = blockIdx.x;
    const int tid = threadIdx.x;
    const int w = tid >> 5, lane = tid & 31;
    float acc = 0.f;
    for (int k = tid; k < GNTILE; k += 256) acc += g_partials[p][k];
    acc = wreduce(acc);
    if (lane == 0) red[w] = acc;
    __syncthreads();
    if (w == 0) {
        float v = (lane < 8) ? red[lane] : 0.f;
        v = wreduce(v);
        if (lane == 0) g_gram[p] = v;
    }
}

// ---------------- Kernel 2: finalize small algebra ----------------
extern "C" __global__ __launch_bounds__(256, 1)
void finalize_kernel(const float* __restrict__ H,
                     const float* __restrict__ wq, const float* __restrict__ wk,
                     const float* __restrict__ bq, const float* __restrict__ bk,
                     const float* __restrict__ cin) {
    __shared__ float Gf[NPAIR];
    __shared__ float h0[16];
    __shared__ float scale[16];
    __shared__ float ubv[2], bnv[2];

    const int tid = threadIdx.x;
    const float cval = cin[0];
    const float Kv = 1.f / cval;
    const float sK = sqrtf(Kv);
    const float onep = 1.f + 1e-7f;

    if (tid < NPAIR) Gf[tid] = g_gram[tid];
    if (tid >= NPAIR && tid < NPAIR + 16) h0[tid - NPAIR] = H[(size_t)(tid - NPAIR) * NND];
    __syncthreads();

    auto GX = [&](int s1, int s2) -> float {
        int a = min(s1, s2), b = max(s1, s2);
        return Gf[(b * (b + 1)) / 2 + a] - h0[s1] * h0[s2];
    };

    if (tid < 16) {
        int s = tid;
        float yn = fmaxf(sqrtf(GX(s, s)), 1e-15f);
        float th = fmaxf(h0[s] / sK, onep);
        float ar = logf(th + sqrtf(fmaxf(th * th - 1.f, 1e-7f)));
        scale[s] = sK * ar / yn;
    }
    __syncthreads();

    if (tid < 32) {
        int r = tid & 15;
        const float* W = (tid < 16) ? wq : wk;
        float* coef = (tid < 16) ? g_coefQ : g_coefK;
        float* first = (tid < 16) ? g_firstQ : g_firstK;
        float Wp[16];
#pragma unroll
        for (int s = 0; s < 16; s++) Wp[s] = W[r * 16 + s] * scale[s];
        float xn2 = 0.f;
        for (int s = 0; s < 16; s++)
            for (int s2 = 0; s2 < 16; s2++)
                xn2 = fmaf(Wp[s] * Wp[s2], GX(s, s2), xn2);
        float xn = fmaxf(sqrtf(xn2), 1e-15f);
        float th = xn / sK;
        float cA = sK * sinhf(th) / xn;
        first[r] = sK * coshf(th);
#pragma unroll
        for (int s = 0; s < 16; s++) coef[r * 16 + s] = cA * Wp[s];
    }
    if (tid == 32 || tid == 33) {
        const float* b = (tid == 32) ? bq : bk;
        float s2 = 0.f;
        for (int j = 1; j < 64; j++) s2 += b[j] * b[j];
        float bn = fmaxf(sqrtf(s2), 1e-15f);
        float tb = fmaxf(b[0] / sK, onep);
        float ub = sK * logf(tb + sqrtf(fmaxf(tb * tb - 1.f, 1e-7f)));
        ubv[tid - 32] = ub;
        bnv[tid - 32] = bn;
    }
    __syncthreads();
    if (tid < 128) {
        int j = tid & 63;
        if (tid < 64) g_uQ[j] = (j == 0) ? 0.f : ubv[0] * bq[j] / bnv[0];
        else          g_uK[j] = (j == 0) ? 0.f : ubv[1] * bk[j] / bnv[1];
    }
}

// ---------------- Kernel 3: fused main, 512 threads, spill-free ----------------
extern "C" __global__ __launch_bounds__(512, 1)
void main_kernel(const float* __restrict__ H, const int* __restrict__ tidx,
                 const float* __restrict__ mask, const float* __restrict__ ain,
                 const float* __restrict__ cin, float* __restrict__ out) {
    extern __shared__ float smem[];
    float* tile = smem;                    // 16*1024
    float* qm   = tile + 16384;            // 16*1024
    float* km   = qm + 16384;              // 16*1024
    float* cQ   = km + 16384;              // 256
    float* cK   = cQ + 256;                // 256
    float* fQ   = cK + 256;                // 16
    float* fK   = fQ + 16;                 // 16
    float* uq   = fK + 16;                 // 64
    float* uk   = uq + 64;                 // 64
    int*   tmA  = (int*)(uk + 64);         // 136
    int*   tnA  = tmA + 136;               // 136
    float* maskS= (float*)(tnA + 136);     // 136
    float* sbuf = maskS + 136;             // 16*136
    float* ssum = sbuf + 16 * 136;         // 16*16
    float* inv0s= ssum + 256;              // 16*16  (becomes z-factor)
    float* lambS= inv0s + 256;             // 16*16  (becomes w-factor)

    const int g = blockIdx.x;
    const int tid = threadIdx.x;
    const int lane = tid & 31, warp = tid >> 5;
    const float cval = __ldg(cin);
    const float aval = __ldg(ain);
    const float Kv = 1.f / cval;
    const float sK = sqrtf(Kv);
    const float onep = 1.f + 1e-7f;

    // ---- load constants + time index ----
    if (tid < 256) { cQ[tid] = g_coefQ[tid]; cK[tid] = g_coefK[tid]; }
    if (tid < 16)  { fQ[tid] = g_firstQ[tid]; fK[tid] = g_firstK[tid]; }
    if (tid < 64)  { uq[tid] = g_uQ[tid]; uk[tid] = g_uK[tid]; }
    bool is64 = (__ldg(&tidx[1]) == 0);   // int64 buffer read as int32 -> high word 0
    if (tid < 136) {
        int tm, tn;
        if (is64) { tm = tidx[2 * tid]; tn = tidx[272 + 2 * tid]; }
        else      { tm = tidx[tid];     tn = tidx[136 + tid]; }
        tmA[tid] = tm; tnA[tid] = tn; maskS[tid] = mask[tid];
    }
    // ---- load big_h tile: samples s*512+g ----
    for (int i = tid; i < 16 * 256; i += 512) {
        int s = i >> 8, c4 = i & 255;
        float4 v = reinterpret_cast<const float4*>(H + (size_t)(s * 512 + g) * 1024)[c4];
        reinterpret_cast<float4*>(tile + s * 1024)[c4] = v;
    }
    __syncthreads();

    // ---- phase 2: 16x16 mix -> q,k raw (packed f32x2) ----
    {
        const float2* t2 = reinterpret_cast<const float2*>(tile);
        float2* q2 = reinterpret_cast<float2*>(qm);
        float2* k2 = reinterpret_cast<float2*>(km);
        ull tv[16];
#pragma unroll
        for (int s = 0; s < 16; s++) {
            float2 v = t2[s * 512 + tid];
            tv[s] = pack2(v.x, v.y);
        }
#pragma unroll
        for (int r = 0; r < 16; r++) {
            const float4* cq4 = reinterpret_cast<const float4*>(cQ + r * 16);
            const float4* ck4 = reinterpret_cast<const float4*>(cK + r * 16);
            ull aq = 0ull, ak = 0ull;
#pragma unroll
            for (int s4 = 0; s4 < 4; s4++) {
                float4 cq = cq4[s4], ck = ck4[s4];
                aq = fma2(pack2(cq.x, cq.x), tv[s4 * 4 + 0], aq);
                aq = fma2(pack2(cq.y, cq.y), tv[s4 * 4 + 1], aq);
                aq = fma2(pack2(cq.z, cq.z), tv[s4 * 4 + 2], aq);
                aq = fma2(pack2(cq.w, cq.w), tv[s4 * 4 + 3], aq);
                ak = fma2(pack2(ck.x, ck.x), tv[s4 * 4 + 0], ak);
                ak = fma2(pack2(ck.y, ck.y), tv[s4 * 4 + 1], ak);
                ak = fma2(pack2(ck.z, ck.z), tv[s4 * 4 + 2], ak);
                ak = fma2(pack2(ck.w, ck.w), tv[s4 * 4 + 3], ak);
            }
            float qlo, qhi, klo, khi;
            unpack2(aq, qlo, qhi);
            unpack2(ak, klo, khi);
            if (g == 0 && tid == 0) { qlo = fQ[r]; klo = fK[r]; }  // expmap0 first column
            q2[r * 512 + tid] = make_float2(qlo, qhi);
            k2[r * 512 + tid] = make_float2(klo, khi);
        }
    }
    __syncthreads();

    // ---- phase 3: mobius_add(b) + proj, thread-per-row, float2, no spills ----
    {
        float* X = (tid < 256) ? qm : km;
        const float* U = (tid < 256) ? uq : uk;
        int rloc = tid & 255;
        float* row = X + (rloc >> 4) * 1024 + (rloc & 15) * 64;
        float2* row2 = reinterpret_cast<float2*>(row);
        const float2* U2 = reinterpret_cast<const float2*>(U);

        float x0 = row[0];   // single conflicted load
        float yn2 = 0.f, du = 0.f;
#pragma unroll
        for (int jp = 0; jp < 32; jp++) {
            int p = (jp + lane) & 31;
            float2 xv = row2[p], uv = U2[p];
            yn2 = fmaf(xv.x, xv.x, fmaf(xv.y, xv.y, yn2));
            du  = fmaf(xv.x, uv.x, fmaf(xv.y, uv.y, du));
        }
        yn2 -= x0 * x0;                 // exclude dim0 (U[0]=0, so du needs no fix)
        float yn = fmaxf(sqrtf(fmaxf(yn2, 0.f)), 1e-15f);
        float alpha = du / (yn * sK);
        float fac = alpha * (sK - x0) / yn;
        float w0p = -fac * x0;          // loop's spurious w at dim0

        float ux = 0.f, w2 = 0.f;
#pragma unroll
        for (int jp = 0; jp < 32; jp++) {
            int p = (jp + lane) & 31;
            float2 xv = row2[p], uv = U2[p];
            float wx = fmaf(-fac, xv.x, uv.x);
            float wy = fmaf(-fac, xv.y, uv.y);
            ux = fmaf(xv.x, wx, fmaf(xv.y, wy, ux));
            w2 = fmaf(wx, wx, fmaf(wy, wy, w2));
        }
        ux -= x0 * w0p;
        w2 -= w0p * w0p;
        float first = ux / fmaxf(x0, 1e-7f);
        float md = fmaxf(w2 - first * first, 1e-7f);
        float nrm = fminf(sqrtf(md), 1e6f);
        float th = fmaxf(nrm / sK, 1e-15f);
        float ch = coshf(th);
        float shn = sinhf(th) / th;

        float r2 = 0.f;
#pragma unroll
        for (int jp = 0; jp < 32; jp++) {
            int p = (jp + lane) & 31;
            float2 xv = row2[p], uv = U2[p];
            float wx = fmaf(-fac, xv.x, uv.x);
            float wy = fmaf(-fac, xv.y, uv.y);
            float rx = fmaf(ch, xv.x, shn * wx);
            float ry = fmaf(ch, xv.y, shn * wy);
            r2 = fmaf(rx, rx, fmaf(ry, ry, r2));
            row2[p] = make_float2(rx, ry);
        }
        float rv0 = fmaf(ch, x0, shn * w0p);
        r2 -= rv0 * rv0;                // exclude spurious dim0
        row[0] = sqrtf(fmaxf(Kv + r2, 1e-7f));   // proj first component
    }
    __syncthreads();

    // ---- phase 4: attention, warp per sample ----
    {
        const int sm = warp;
        const float* tsm = tile + sm * 1024;

        // lorenz factor + 1/x0, lanes 0..15 (lane = tt), rotated conflict-free
        if (lane < 16) {
            const float* bp = tsm + lane * 64;
            float h0v = bp[0];
            float iv = 1.f / h0v;
            float sv = 0.f;
#pragma unroll
            for (int d0 = 0; d0 < 64; d0++) {
                int d = (d0 + lane) & 63;
                float v = bp[d] * iv;
                if (d != 0) sv = fmaf(v, v, sv);
            }
            lambS[sm * 16 + lane] = 1.f / sqrtf(1.f - fminf(sv, 0.9f));
            inv0s[sm * 16 + lane] = iv;
        }
        __syncwarp();

        // s[e] = exp(-a*sqdist - c + mask), float2 dot
        const float* qs = qm + sm * 1024;
        const float* ks = km + sm * 1024;
        for (int base = 0; base < 160; base += 32) {
            int e = base + lane;
            bool val = e < 136;
            int m  = val ? tmA[e] : 0;
            int n2 = val ? tnA[e] : 0;
            const float2* qr2 = reinterpret_cast<const float2*>(qs + m * 64);
            const float2* kr2 = reinterpret_cast<const float2*>(ks + n2 * 64);
            float acc = 0.f, q0 = 0.f, k0 = 0.f;
#pragma unroll
            for (int pp = 0; pp < 32; pp++) {
                int p = (pp + lane) & 31;
                float2 qv = qr2[p], kv = kr2[p];
                if (p == 0) { q0 = qv.x; k0 = kv.x; }
                acc = fmaf(qv.x, kv.x, fmaf(qv.y, kv.y, acc));
            }
            if (val) {
                float mdot = acc - 2.f * q0 * k0;
                float thv = fmaxf(-mdot * cval, onep);
                float ar = logf(thv + sqrtf(fmaxf(thv * thv - 1.f, 1e-7f)));
                float sq = fminf(Kv * ar * ar, 50.f);
                sbuf[sm * 136 + e] = expf(fmaf(-aval, sq, maskS[e] - cval));
            }
        }
        __syncwarp();

        // s_sum per m: all 32 lanes participate (half range each), pairwise combine
        {
            int mm = lane & 15;
            int lo = (lane < 16) ? 0 : 68;
            int hi = (lane < 16) ? 68 : 136;
            float acc = 0.f;
            for (int e = lo; e < hi; e++)
                if (tmA[e] == mm) acc += sbuf[sm * 136 + e];
            acc += __shfl_xor_sync(0xffffffffu, acc, 16);
            if (lane < 16) ssum[sm * 16 + mm] = acc;
        }
        __syncwarp();

        // fold per-tn factors in place: lambS -> w-factor, inv0s -> z-factor
        if (lane < 16) {
            float f = lambS[sm * 16 + lane] / ssum[sm * 16 + lane];
            lambS[sm * 16 + lane] = f;
            inv0s[sm * 16 + lane] = f * inv0s[sm * 16 + lane];
        }
        __syncwarp();

        // z/w scatter by contiguous t_m runs, flush -> k2h -> global
        int cur = tmA[0];
        float a0 = 0.f, a1 = 0.f;  // a0: dim lane; a1: dim lane+32 (lane<31) or w_sum (lane 31)
        const size_t obase = (size_t)(sm * 512 + g) * 1024;
        for (int e = 0; e <= 136; ++e) {
            int me = (e < 136) ? tmA[e] : -1;
            if (me != cur) {
                float wsum = __shfl_sync(0xffffffffu, a1, 31);
                float o0 = a0 / wsum;
                float o1 = (lane < 31) ? a1 / wsum : 0.f;
                float s2 = wreduce(o0 * o0 + o1 * o1);
                float inv = 1.f / sqrtf(1.f - fminf(s2, 0.999f));
                float* op = out + obase + (size_t)cur * 64;
                op[1 + lane] = o0 * inv;
                if (lane < 31) op[33 + lane] = o1 * inv;
                if (lane == 0) op[0] = inv;
                cur = me; a0 = 0.f; a1 = 0.f;
                if (e == 136) break;
            }
            float se = sbuf[sm * 136 + e];
            int tn = tnA[e];
            float fz = se * inv0s[sm * 16 + tn];
            const float* hr = tsm + tn * 64;
            a0 = fmaf(fz, hr[1 + lane], a0);
            a1 = (lane < 31) ? fmaf(fz, hr[33 + lane], a1)
                             : fmaf(se, lambS[sm * 16 + tn], a1);
        }
    }
}

// ---------------- launch ----------------
extern "C" void kernel_launch(void* const* d_in, const int* in_sizes, int n_in,
                              void* d_out, int out_size) {
    (void)in_sizes; (void)n_in; (void)out_size;
    const float* H    = (const float*)d_in[0];
    const int*   tidx = (const int*)d_in[1];
    const float* mask = (const float*)d_in[2];
    const float* wq   = (const float*)d_in[3];
    const float* wk   = (const float*)d_in[4];
    const float* bq   = (const float*)d_in[5];
    const float* bk   = (const float*)d_in[6];
    const float* a    = (const float*)d_in[7];
    const float* c    = (const float*)d_in[8];
    float* out = (float*)d_out;

    const int MAIN_FLOATS = 3 * 16384 + 256 + 256 + 16 + 16 + 64 + 64
                            + 136 + 136 + 136 + 16 * 136 + 256 + 256 + 256;
    const int MAIN_SMEM = MAIN_FLOATS * 4;   // ~208KB

    cudaFuncSetAttribute(main_kernel, cudaFuncAttributeMaxDynamicSharedMemorySize, MAIN_SMEM);

    gram_kernel<<<GNTILE, 320>>>(H);
    reduce_kernel<<<NPAIR, 256>>>();
    finalize_kernel<<<1, 256>>>(H, wq, wk, bq, bk, c);
    main_kernel<<<512, 512, MAIN_SMEM>>>(H, tidx, mask, a, c, out);
}

// round 9
// speedup vs baseline: 3.8750x; 1.2844x over previous
#include <cuda_runtime.h>
#include <math.h>

// Problem constants (fixed by dataset)
#define NSAMP 8192
#define NND  (NSAMP * 64)        // 524288 (giant row length)
#define NPAIR 136                // 16*17/2 gram pairs
#define GTILE_COLS 512           // cols per gram block
#define GNTILE 1024              // 524288 / 512

// ---------------- device globals (scratch, statically allocated) ----------------
__device__ float g_partials[NPAIR][GNTILE];
__device__ float g_gram[NPAIR];
__device__ float g_coefQ[256];
__device__ float g_coefK[256];
__device__ float g_firstQ[16];
__device__ float g_firstK[16];
__device__ float g_uQ[64];
__device__ float g_uK[64];
__device__ float g_u2[2];        // ||u||^2 (dims 1..63) for q,k

typedef unsigned long long ull;

__device__ __forceinline__ float wreduce(float v) {
#pragma unroll
    for (int o = 16; o; o >>= 1) v += __shfl_xor_sync(0xffffffffu, v, o);
    return v;
}

__device__ __forceinline__ ull fma2(ull a, ull b, ull c) {
    ull d; asm("fma.rn.f32x2 %0, %1, %2, %3;" : "=l"(d) : "l"(a), "l"(b), "l"(c));
    return d;
}
__device__ __forceinline__ ull pack2(float lo, float hi) {
    ull d; asm("mov.b64 %0, {%1, %2};" : "=l"(d) : "f"(lo), "f"(hi));
    return d;
}
__device__ __forceinline__ void unpack2(ull v, float& lo, float& hi) {
    asm("mov.b64 {%0, %1}, %2;" : "=f"(lo), "=f"(hi) : "l"(v));
}

// ---------------- Kernel 1: Gram partials, warp-per-4x4-block (10 warps) ----------------
extern "C" __global__ __launch_bounds__(320)
void gram_kernel(const float* __restrict__ H) {
    __shared__ float gt[16 * GTILE_COLS];   // 32KB
    const int b = blockIdx.x;
    const int tid = threadIdx.x;

    const float4* H4 = reinterpret_cast<const float4*>(H);
    for (int i = tid; i < 16 * (GTILE_COLS / 4); i += 320) {
        int s = i >> 7;
        int c4 = i & 127;
        reinterpret_cast<float4*>(gt + s * GTILE_COLS)[c4] =
            H4[(size_t)s * (NND / 4) + (size_t)b * (GTILE_COLS / 4) + c4];
    }
    __syncthreads();

    const int w = tid >> 5, lane = tid & 31;
    const int bi_arr[10] = {0, 1, 1, 2, 2, 2, 3, 3, 3, 3};
    const int bj_arr[10] = {0, 0, 1, 0, 1, 2, 0, 1, 2, 3};
    const int bi = bi_arr[w], bj = bj_arr[w];

    const float* A  = gt + (bi * 4) * GTILE_COLS + lane;
    const float* Bp = gt + (bj * 4) * GTILE_COLS + lane;
    float acc[16];
#pragma unroll
    for (int i = 0; i < 16; i++) acc[i] = 0.f;
#pragma unroll
    for (int c = 0; c < GTILE_COLS; c += 32) {
        float a0 = A[c], a1 = A[c + GTILE_COLS], a2 = A[c + 2 * GTILE_COLS], a3 = A[c + 3 * GTILE_COLS];
        float b0 = Bp[c], b1 = Bp[c + GTILE_COLS], b2 = Bp[c + 2 * GTILE_COLS], b3 = Bp[c + 3 * GTILE_COLS];
        acc[0]  = fmaf(a0, b0, acc[0]);   acc[1]  = fmaf(a0, b1, acc[1]);
        acc[2]  = fmaf(a0, b2, acc[2]);   acc[3]  = fmaf(a0, b3, acc[3]);
        acc[4]  = fmaf(a1, b0, acc[4]);   acc[5]  = fmaf(a1, b1, acc[5]);
        acc[6]  = fmaf(a1, b2, acc[6]);   acc[7]  = fmaf(a1, b3, acc[7]);
        acc[8]  = fmaf(a2, b0, acc[8]);   acc[9]  = fmaf(a2, b1, acc[9]);
        acc[10] = fmaf(a2, b2, acc[10]);  acc[11] = fmaf(a2, b3, acc[11]);
        acc[12] = fmaf(a3, b0, acc[12]);  acc[13] = fmaf(a3, b1, acc[13]);
        acc[14] = fmaf(a3, b2, acc[14]);  acc[15] = fmaf(a3, b3, acc[15]);
    }
#pragma unroll
    for (int ki = 0; ki < 4; ki++) {
#pragma unroll
        for (int kj = 0; kj < 4; kj++) {
            float v = wreduce(acc[ki * 4 + kj]);
            int s2 = bi * 4 + ki, s1 = bj * 4 + kj;
            if (lane == 0 && s1 <= s2)
                g_partials[(s2 * (s2 + 1)) / 2 + s1][b] = v;
        }
    }
}

// ---------------- Kernel 1b: parallel deterministic reduction of partials ----------------
extern "C" __global__ __launch_bounds__(256)
void reduce_kernel() {
    __shared__ float red[8];
    const int p = blockIdx.x;
    const int tid = threadIdx.x;
    const int w = tid >> 5, lane = tid & 31;
    float acc = 0.f;
    for (int k = tid; k < GNTILE; k += 256) acc += g_partials[p][k];
    acc = wreduce(acc);
    if (lane == 0) red[w] = acc;
    __syncthreads();
    if (w == 0) {
        float v = (lane < 8) ? red[lane] : 0.f;
        v = wreduce(v);
        if (lane == 0) g_gram[p] = v;
    }
}

// ---------------- Kernel 2: finalize small algebra ----------------
extern "C" __global__ __launch_bounds__(256, 1)
void finalize_kernel(const float* __restrict__ H,
                     const float* __restrict__ wq, const float* __restrict__ wk,
                     const float* __restrict__ bq, const float* __restrict__ bk,
                     const float* __restrict__ cin) {
    __shared__ float Gf[NPAIR];
    __shared__ float h0[16];
    __shared__ float scale[16];
    __shared__ float ubv[2], bnv[2];

    const int tid = threadIdx.x;
    const float cval = cin[0];
    const float Kv = 1.f / cval;
    const float sK = sqrtf(Kv);
    const float onep = 1.f + 1e-7f;

    if (tid < NPAIR) Gf[tid] = g_gram[tid];
    if (tid >= NPAIR && tid < NPAIR + 16) h0[tid - NPAIR] = H[(size_t)(tid - NPAIR) * NND];
    __syncthreads();

    auto GX = [&](int s1, int s2) -> float {
        int a = min(s1, s2), b = max(s1, s2);
        return Gf[(b * (b + 1)) / 2 + a] - h0[s1] * h0[s2];
    };

    if (tid < 16) {
        int s = tid;
        float yn = fmaxf(sqrtf(GX(s, s)), 1e-15f);
        float th = fmaxf(h0[s] / sK, onep);
        float ar = logf(th + sqrtf(fmaxf(th * th - 1.f, 1e-7f)));
        scale[s] = sK * ar / yn;
    }
    __syncthreads();

    if (tid < 32) {
        int r = tid & 15;
        const float* W = (tid < 16) ? wq : wk;
        float* coef = (tid < 16) ? g_coefQ : g_coefK;
        float* first = (tid < 16) ? g_firstQ : g_firstK;
        float Wp[16];
#pragma unroll
        for (int s = 0; s < 16; s++) Wp[s] = W[r * 16 + s] * scale[s];
        float xn2 = 0.f;
        for (int s = 0; s < 16; s++)
            for (int s2 = 0; s2 < 16; s2++)
                xn2 = fmaf(Wp[s] * Wp[s2], GX(s, s2), xn2);
        float xn = fmaxf(sqrtf(xn2), 1e-15f);
        float th = xn / sK;
        float cA = sK * sinhf(th) / xn;
        first[r] = sK * coshf(th);
#pragma unroll
        for (int s = 0; s < 16; s++) coef[r * 16 + s] = cA * Wp[s];
    }
    if (tid == 32 || tid == 33) {
        const float* b = (tid == 32) ? bq : bk;
        float s2 = 0.f;
        for (int j = 1; j < 64; j++) s2 += b[j] * b[j];
        float bn = fmaxf(sqrtf(s2), 1e-15f);
        float tb = fmaxf(b[0] / sK, onep);
        float ub = sK * logf(tb + sqrtf(fmaxf(tb * tb - 1.f, 1e-7f)));
        ubv[tid - 32] = ub;
        bnv[tid - 32] = bn;
        g_u2[tid - 32] = ub * ub;     // ||u||^2 = ub^2 since u = ub * y/||y||
    }
    __syncthreads();
    if (tid < 128) {
        int j = tid & 63;
        if (tid < 64) g_uQ[j] = (j == 0) ? 0.f : ubv[0] * bq[j] / bnv[0];
        else          g_uK[j] = (j == 0) ? 0.f : ubv[1] * bk[j] / bnv[1];
    }
}

// ---------------- Kernel 3: fused main, 512 threads ----------------
extern "C" __global__ __launch_bounds__(512, 1)
void main_kernel(const float* __restrict__ H, const int* __restrict__ tidx,
                 const float* __restrict__ mask, const float* __restrict__ ain,
                 const float* __restrict__ cin, float* __restrict__ out) {
    extern __shared__ float smem[];
    float* tile = smem;                    // 16*1024
    float* qm   = tile + 16384;            // 16*1024
    float* km   = qm + 16384;              // 16*1024
    float* cQ   = km + 16384;              // 256
    float* cK   = cQ + 256;                // 256
    float* fQ   = cK + 256;                // 16
    float* fK   = fQ + 16;                 // 16
    float* uq   = fK + 16;                 // 64
    float* uk   = uq + 64;                 // 64
    int*   tmA  = (int*)(uk + 64);         // 136
    int*   tnA  = tmA + 136;               // 136
    float* maskS= (float*)(tnA + 136);     // 136
    float* sbuf = maskS + 136;             // 16*136
    float* ssum = sbuf + 16 * 136;         // 16*16
    float* zfac = ssum + 256;              // 16*16 (lamb/ssum * 1/h0)
    float* wfac = zfac + 256;              // 16*16 (lamb/ssum)
    float* firsts = wfac + 256;            // 512: [qk*256 + samp*16 + tt] post-proj x0

    const int g = blockIdx.x;
    const int tid = threadIdx.x;
    const int lane = tid & 31, warp = tid >> 5;
    const float cval = __ldg(cin);
    const float aval = __ldg(ain);
    const float Kv = 1.f / cval;
    const float sK = sqrtf(Kv);
    const float onep = 1.f + 1e-7f;

    // ---- load constants + time index ----
    if (tid < 256) { cQ[tid] = g_coefQ[tid]; cK[tid] = g_coefK[tid]; }
    if (tid < 16)  { fQ[tid] = g_firstQ[tid]; fK[tid] = g_firstK[tid]; }
    if (tid < 64)  { uq[tid] = g_uQ[tid]; uk[tid] = g_uK[tid]; }
    bool is64 = (__ldg(&tidx[1]) == 0);   // int64 buffer read as int32 -> high word 0
    if (tid < 136) {
        int tm, tn;
        if (is64) { tm = tidx[2 * tid]; tn = tidx[272 + 2 * tid]; }
        else      { tm = tidx[tid];     tn = tidx[136 + tid]; }
        tmA[tid] = tm; tnA[tid] = tn; maskS[tid] = mask[tid];
    }
    // ---- load big_h tile: samples s*512+g ----
    for (int i = tid; i < 16 * 256; i += 512) {
        int s = i >> 8, c4 = i & 255;
        float4 v = reinterpret_cast<const float4*>(H + (size_t)(s * 512 + g) * 1024)[c4];
        reinterpret_cast<float4*>(tile + s * 1024)[c4] = v;
    }
    __syncthreads();

    // ---- phase 2: 16x16 mix -> q,k raw (packed f32x2) ----
    {
        const float2* t2 = reinterpret_cast<const float2*>(tile);
        float2* q2 = reinterpret_cast<float2*>(qm);
        float2* k2 = reinterpret_cast<float2*>(km);
        ull tv[16];
#pragma unroll
        for (int s = 0; s < 16; s++) {
            float2 v = t2[s * 512 + tid];
            tv[s] = pack2(v.x, v.y);
        }
#pragma unroll
        for (int r = 0; r < 16; r++) {
            const float4* cq4 = reinterpret_cast<const float4*>(cQ + r * 16);
            const float4* ck4 = reinterpret_cast<const float4*>(cK + r * 16);
            ull aq = 0ull, ak = 0ull;
#pragma unroll
            for (int s4 = 0; s4 < 4; s4++) {
                float4 cq = cq4[s4], ck = ck4[s4];
                aq = fma2(pack2(cq.x, cq.x), tv[s4 * 4 + 0], aq);
                aq = fma2(pack2(cq.y, cq.y), tv[s4 * 4 + 1], aq);
                aq = fma2(pack2(cq.z, cq.z), tv[s4 * 4 + 2], aq);
                aq = fma2(pack2(cq.w, cq.w), tv[s4 * 4 + 3], aq);
                ak = fma2(pack2(ck.x, ck.x), tv[s4 * 4 + 0], ak);
                ak = fma2(pack2(ck.y, ck.y), tv[s4 * 4 + 1], ak);
                ak = fma2(pack2(ck.z, ck.z), tv[s4 * 4 + 2], ak);
                ak = fma2(pack2(ck.w, ck.w), tv[s4 * 4 + 3], ak);
            }
            float qlo, qhi, klo, khi;
            unpack2(aq, qlo, qhi);
            unpack2(ak, klo, khi);
            if (g == 0 && tid == 0) { qlo = fQ[r]; klo = fK[r]; }  // expmap0 first column
            q2[r * 512 + tid] = make_float2(qlo, qhi);
            k2[r * 512 + tid] = make_float2(klo, khi);
        }
    }
    __syncthreads();

    // ---- phase 3: mobius_add(b) + proj, thread-per-row, closed-form reductions ----
    {
        float* X = (tid < 256) ? qm : km;
        const float4* U4 = reinterpret_cast<const float4*>((tid < 256) ? uq : uk);
        const float u2 = (tid < 256) ? g_u2[0] : g_u2[1];
        int rloc = tid & 255;
        float* row = X + (rloc >> 4) * 1024 + (rloc & 15) * 64;
        float4* row4 = reinterpret_cast<float4*>(row);

        float x0 = 0.f;
        float yn2a = 0.f, yn2b = 0.f, dua = 0.f, dub = 0.f;
#pragma unroll
        for (int jp = 0; jp < 16; jp++) {
            int p = (jp + lane) & 15;
            float4 xv = row4[p];
            float4 uv = U4[p];
            if (p == 0) x0 = xv.x;
            yn2a = fmaf(xv.x, xv.x, fmaf(xv.y, xv.y, yn2a));
            yn2b = fmaf(xv.z, xv.z, fmaf(xv.w, xv.w, yn2b));
            dua  = fmaf(xv.x, uv.x, fmaf(xv.y, uv.y, dua));
            dub  = fmaf(xv.z, uv.z, fmaf(xv.w, uv.w, dub));
        }
        float yn2 = (yn2a + yn2b) - x0 * x0;     // exclude dim0 (U[0]=0 so du is fine)
        float du  = dua + dub;

        float yn = fmaxf(sqrtf(fmaxf(yn2, 0.f)), 1e-15f);
        float alpha = du / (yn * sK);
        float fac = alpha * (sK - x0) / yn;
        float ux = du - fac * yn2;                       // x.(u - fac x) excl dim0
        float first = ux / fmaxf(x0, 1e-7f);
        float w2 = fmaf(fac * fac, yn2, fmaf(-2.f * fac, du, u2));  // |u-fac x|^2 excl dim0
        float md = fmaxf(w2 - first * first, 1e-7f);
        float nrm = fminf(sqrtf(md), 1e6f);
        float th = fmaxf(nrm / sK, 1e-15f);
        float ch = coshf(th);
        float shn = sinhf(th) / th;
        float A = fmaf(-shn, fac, ch);                   // rv = A*x + B*u
        float B = shn;
        float r2 = fmaf(A * A, yn2, fmaf(2.f * A * B, du, B * B * u2));
        float o0 = sqrtf(fmaxf(Kv + r2, 1e-7f));

#pragma unroll
        for (int jp = 0; jp < 16; jp++) {
            int p = (jp + lane) & 15;
            float4 xv = row4[p];
            float4 uv = U4[p];
            float4 rv;
            rv.x = fmaf(A, xv.x, B * uv.x);
            rv.y = fmaf(A, xv.y, B * uv.y);
            rv.z = fmaf(A, xv.z, B * uv.z);
            rv.w = fmaf(A, xv.w, B * uv.w);
            row4[p] = rv;
        }
        row[0] = o0;
        firsts[((tid < 256) ? 0 : 256) + rloc] = o0;
    }
    __syncthreads();

    // ---- phase 4: attention, warp per sample ----
    {
        const int sm = warp;
        const float* tsm = tile + sm * 1024;

        // lorenz factor + 1/x0: all 32 lanes (2 half-rows per tt), float4 rotated
        {
            int ttv = lane & 15, half = lane >> 4;
            const float4* bp4 = reinterpret_cast<const float4*>(tsm + ttv * 64 + half * 32);
            float h0c = 0.f, sva = 0.f, svb = 0.f;
#pragma unroll
            for (int j = 0; j < 8; j++) {
                int p = (j + ttv) & 7;
                float4 v = bp4[p];
                if (half == 0 && p == 0) h0c = v.x;
                sva = fmaf(v.x, v.x, fmaf(v.y, v.y, sva));
                svb = fmaf(v.z, v.z, fmaf(v.w, v.w, svb));
            }
            float sv = sva + svb;
            float h0v = __shfl_sync(0xffffffffu, h0c, ttv);
            sv += __shfl_xor_sync(0xffffffffu, sv, 16);
            float iv = 1.f / h0v;
            if (half == 0) {
                float svn = (sv - h0v * h0v) * iv * iv;
                wfac[sm * 16 + ttv] = rsqrtf(1.f - fminf(svn, 0.9f));  // lamb (pre-fold)
                zfac[sm * 16 + ttv] = iv;                              // 1/h0 (pre-fold)
            }
        }
        __syncwarp();

        // s[e] = exp(-a*sqdist - c + mask), float4 dot, dual accumulators
        const float* qs = qm + sm * 1024;
        const float* ks = km + sm * 1024;
        for (int base = 0; base < 160; base += 32) {
            int e = base + lane;
            if (e < 136) {
                int m = tmA[e], n2 = tnA[e];
                const float4* qr4 = reinterpret_cast<const float4*>(qs + m * 64);
                const float4* kr4 = reinterpret_cast<const float4*>(ks + n2 * 64);
                float accA = 0.f, accB = 0.f;
#pragma unroll
                for (int pp = 0; pp < 16; ++pp) {
                    int p = (pp + lane) & 15;
                    float4 qv = qr4[p], kv = kr4[p];
                    accA = fmaf(qv.x, kv.x, fmaf(qv.y, kv.y, accA));
                    accB = fmaf(qv.z, kv.z, fmaf(qv.w, kv.w, accB));
                }
                float q0 = firsts[sm * 16 + m];
                float k0 = firsts[256 + sm * 16 + n2];
                float mdot = (accA + accB) - 2.f * q0 * k0;
                float thv = fmaxf(-mdot * cval, onep);
                float ar = __logf(thv + sqrtf(fmaxf(thv * thv - 1.f, 1e-7f)));
                float sq = fminf(Kv * ar * ar, 50.f);
                sbuf[sm * 136 + e] = __expf(fmaf(-aval, sq, maskS[e] - cval));
            }
        }
        __syncwarp();

        // s_sum per m: 32 lanes, half range each, pairwise combine
        {
            int mm = lane & 15;
            int lo = (lane < 16) ? 0 : 68;
            int hi = (lane < 16) ? 68 : 136;
            float acc = 0.f;
            for (int e = lo; e < hi; e++)
                if (tmA[e] == mm) acc += sbuf[sm * 136 + e];
            acc += __shfl_xor_sync(0xffffffffu, acc, 16);
            if (lane < 16) ssum[sm * 16 + mm] = acc;
        }
        __syncwarp();

        // fold: wfac = lamb/ssum, zfac = lamb/ssum * (1/h0)
        if (lane < 16) {
            float f = wfac[sm * 16 + lane] / ssum[sm * 16 + lane];
            wfac[sm * 16 + lane] = f;
            zfac[sm * 16 + lane] = f * zfac[sm * 16 + lane];
        }
        __syncwarp();

        // z/w scatter by contiguous t_m runs; lane holds dims (2l, 2l+1); dim0 junk fixed at flush
        const float2* tsm2 = reinterpret_cast<const float2*>(tsm);
        int cur = tmA[0];
        float2 az = make_float2(0.f, 0.f);
        float wacc = 0.f;     // redundantly identical on all lanes
        const size_t obase = (size_t)(sm * 512 + g) * 1024;
        for (int e = 0; e <= 136; ++e) {
            int me = (e < 136) ? tmA[e] : -1;
            if (me != cur) {
                float iw = __fdividef(1.f, wacc);
                float ox = az.x * iw, oy = az.y * iw;
                float contrib = (lane == 0) ? oy * oy : fmaf(ox, ox, oy * oy);
                float s2 = wreduce(contrib);
                float inv = rsqrtf(1.f - fminf(s2, 0.999f));
                float2 ov = make_float2(ox * inv, oy * inv);
                if (lane == 0) ov.x = inv;   // out[0] = lorenz of result
                reinterpret_cast<float2*>(out + obase + (size_t)cur * 64)[lane] = ov;
                cur = me; az = make_float2(0.f, 0.f); wacc = 0.f;
                if (e == 136) break;
            }
            float se = sbuf[sm * 136 + e];
            int tn = tnA[e];
            float fz = se * zfac[sm * 16 + tn];
            wacc = fmaf(se, wfac[sm * 16 + tn], wacc);
            float2 hv = tsm2[tn * 32 + lane];
            az.x = fmaf(fz, hv.x, az.x);
            az.y = fmaf(fz, hv.y, az.y);
        }
    }
}

// ---------------- launch ----------------
extern "C" void kernel_launch(void* const* d_in, const int* in_sizes, int n_in,
                              void* d_out, int out_size) {
    (void)in_sizes; (void)n_in; (void)out_size;
    const float* H    = (const float*)d_in[0];
    const int*   tidx = (const int*)d_in[1];
    const float* mask = (const float*)d_in[2];
    const float* wq   = (const float*)d_in[3];
    const float* wk   = (const float*)d_in[4];
    const float* bq   = (const float*)d_in[5];
    const float* bk   = (const float*)d_in[6];
    const float* a    = (const float*)d_in[7];
    const float* c    = (const float*)d_in[8];
    float* out = (float*)d_out;

    const int MAIN_FLOATS = 3 * 16384 + 256 + 256 + 16 + 16 + 64 + 64
                            + 136 + 136 + 136 + 16 * 136 + 256 + 256 + 256 + 512;
    const int MAIN_SMEM = MAIN_FLOATS * 4;   // ~210KB

    cudaFuncSetAttribute(main_kernel, cudaFuncAttributeMaxDynamicSharedMemorySize, MAIN_SMEM);

    gram_kernel<<<GNTILE, 320>>>(H);
    reduce_kernel<<<NPAIR, 256>>>();
    finalize_kernel<<<1, 256>>>(H, wq, wk, bq, bk, c);
    main_kernel<<<512, 512, MAIN_SMEM>>>(H, tidx, mask, a, c, out);
}

// round 10
// speedup vs baseline: 5.4151x; 1.3974x over previous
#include <cuda_runtime.h>
#include <math.h>

// Problem constants (fixed by dataset)
#define NSAMP 8192
#define NND  (NSAMP * 64)        // 524288 (giant row length)
#define NPAIR 136                // 16*17/2 gram pairs
#define GTILE_COLS 512           // cols per gram block
#define GNTILE 1024              // 524288 / 512

// ---------------- device globals (scratch, statically allocated) ----------------
__device__ float g_partials[NPAIR][GNTILE];
__device__ float g_gram[NPAIR];
__device__ float g_coefQ[256];
__device__ float g_coefK[256];
__device__ float g_firstQ[16];
__device__ float g_firstK[16];
__device__ float g_uQ[64];
__device__ float g_uK[64];
__device__ float g_u2[2];        // ||u||^2 (dims 1..63) for q,k

typedef unsigned long long ull;

__device__ __forceinline__ float wreduce(float v) {
#pragma unroll
    for (int o = 16; o; o >>= 1) v += __shfl_xor_sync(0xffffffffu, v, o);
    return v;
}

__device__ __forceinline__ ull fma2(ull a, ull b, ull c) {
    ull d; asm("fma.rn.f32x2 %0, %1, %2, %3;" : "=l"(d) : "l"(a), "l"(b), "l"(c));
    return d;
}
__device__ __forceinline__ ull pack2(float lo, float hi) {
    ull d; asm("mov.b64 %0, {%1, %2};" : "=l"(d) : "f"(lo), "f"(hi));
    return d;
}
__device__ __forceinline__ void unpack2(ull v, float& lo, float& hi) {
    asm("mov.b64 {%0, %1}, %2;" : "=f"(lo), "=f"(hi) : "l"(v));
}

// ---------------- Kernel 1: Gram partials, warp-per-4x4-block (10 warps) ----------------
extern "C" __global__ __launch_bounds__(320)
void gram_kernel(const float* __restrict__ H) {
    __shared__ float gt[16 * GTILE_COLS];   // 32KB
    const int b = blockIdx.x;
    const int tid = threadIdx.x;

    const float4* H4 = reinterpret_cast<const float4*>(H);
    for (int i = tid; i < 16 * (GTILE_COLS / 4); i += 320) {
        int s = i >> 7;
        int c4 = i & 127;
        reinterpret_cast<float4*>(gt + s * GTILE_COLS)[c4] =
            H4[(size_t)s * (NND / 4) + (size_t)b * (GTILE_COLS / 4) + c4];
    }
    __syncthreads();

    const int w = tid >> 5, lane = tid & 31;
    const int bi_arr[10] = {0, 1, 1, 2, 2, 2, 3, 3, 3, 3};
    const int bj_arr[10] = {0, 0, 1, 0, 1, 2, 0, 1, 2, 3};
    const int bi = bi_arr[w], bj = bj_arr[w];

    const float* A  = gt + (bi * 4) * GTILE_COLS + lane;
    const float* Bp = gt + (bj * 4) * GTILE_COLS + lane;
    float acc[16];
#pragma unroll
    for (int i = 0; i < 16; i++) acc[i] = 0.f;
#pragma unroll
    for (int c = 0; c < GTILE_COLS; c += 32) {
        float a0 = A[c], a1 = A[c + GTILE_COLS], a2 = A[c + 2 * GTILE_COLS], a3 = A[c + 3 * GTILE_COLS];
        float b0 = Bp[c], b1 = Bp[c + GTILE_COLS], b2 = Bp[c + 2 * GTILE_COLS], b3 = Bp[c + 3 * GTILE_COLS];
        acc[0]  = fmaf(a0, b0, acc[0]);   acc[1]  = fmaf(a0, b1, acc[1]);
        acc[2]  = fmaf(a0, b2, acc[2]);   acc[3]  = fmaf(a0, b3, acc[3]);
        acc[4]  = fmaf(a1, b0, acc[4]);   acc[5]  = fmaf(a1, b1, acc[5]);
        acc[6]  = fmaf(a1, b2, acc[6]);   acc[7]  = fmaf(a1, b3, acc[7]);
        acc[8]  = fmaf(a2, b0, acc[8]);   acc[9]  = fmaf(a2, b1, acc[9]);
        acc[10] = fmaf(a2, b2, acc[10]);  acc[11] = fmaf(a2, b3, acc[11]);
        acc[12] = fmaf(a3, b0, acc[12]);  acc[13] = fmaf(a3, b1, acc[13]);
        acc[14] = fmaf(a3, b2, acc[14]);  acc[15] = fmaf(a3, b3, acc[15]);
    }
#pragma unroll
    for (int ki = 0; ki < 4; ki++) {
#pragma unroll
        for (int kj = 0; kj < 4; kj++) {
            float v = wreduce(acc[ki * 4 + kj]);
            int s2 = bi * 4 + ki, s1 = bj * 4 + kj;
            if (lane == 0 && s1 <= s2)
                g_partials[(s2 * (s2 + 1)) / 2 + s1][b] = v;
        }
    }
}

// ---------------- Kernel 1b: parallel deterministic reduction of partials ----------------
extern "C" __global__ __launch_bounds__(256)
void reduce_kernel() {
    __shared__ float red[8];
    const int p = blockIdx.x;
    const int tid = threadIdx.x;
    const int w = tid >> 5, lane = tid & 31;
    float acc = 0.f;
    for (int k = tid; k < GNTILE; k += 256) acc += g_partials[p][k];
    acc = wreduce(acc);
    if (lane == 0) red[w] = acc;
    __syncthreads();
    if (w == 0) {
        float v = (lane < 8) ? red[lane] : 0.f;
        v = wreduce(v);
        if (lane == 0) g_gram[p] = v;
    }
}

// ---------------- Kernel 2: finalize small algebra ----------------
extern "C" __global__ __launch_bounds__(256, 1)
void finalize_kernel(const float* __restrict__ H,
                     const float* __restrict__ wq, const float* __restrict__ wk,
                     const float* __restrict__ bq, const float* __restrict__ bk,
                     const float* __restrict__ cin) {
    __shared__ float Gf[NPAIR];
    __shared__ float h0[16];
    __shared__ float scale[16];
    __shared__ float ubv[2], bnv[2];

    const int tid = threadIdx.x;
    const float cval = cin[0];
    const float Kv = 1.f / cval;
    const float sK = sqrtf(Kv);
    const float onep = 1.f + 1e-7f;

    if (tid < NPAIR) Gf[tid] = g_gram[tid];
    if (tid >= NPAIR && tid < NPAIR + 16) h0[tid - NPAIR] = H[(size_t)(tid - NPAIR) * NND];
    __syncthreads();

    auto GX = [&](int s1, int s2) -> float {
        int a = min(s1, s2), b = max(s1, s2);
        return Gf[(b * (b + 1)) / 2 + a] - h0[s1] * h0[s2];
    };

    if (tid < 16) {
        int s = tid;
        float yn = fmaxf(sqrtf(GX(s, s)), 1e-15f);
        float th = fmaxf(h0[s] / sK, onep);
        float ar = logf(th + sqrtf(fmaxf(th * th - 1.f, 1e-7f)));
        scale[s] = sK * ar / yn;
    }
    __syncthreads();

    if (tid < 32) {
        int r = tid & 15;
        const float* W = (tid < 16) ? wq : wk;
        float* coef = (tid < 16) ? g_coefQ : g_coefK;
        float* first = (tid < 16) ? g_firstQ : g_firstK;
        float Wp[16];
#pragma unroll
        for (int s = 0; s < 16; s++) Wp[s] = W[r * 16 + s] * scale[s];
        float xn2 = 0.f;
        for (int s = 0; s < 16; s++)
            for (int s2 = 0; s2 < 16; s2++)
                xn2 = fmaf(Wp[s] * Wp[s2], GX(s, s2), xn2);
        float xn = fmaxf(sqrtf(xn2), 1e-15f);
        float th = xn / sK;
        float cA = sK * sinhf(th) / xn;
        first[r] = sK * coshf(th);
#pragma unroll
        for (int s = 0; s < 16; s++) coef[r * 16 + s] = cA * Wp[s];
    }
    if (tid == 32 || tid == 33) {
        const float* b = (tid == 32) ? bq : bk;
        float s2 = 0.f;
        for (int j = 1; j < 64; j++) s2 += b[j] * b[j];
        float bn = fmaxf(sqrtf(s2), 1e-15f);
        float tb = fmaxf(b[0] / sK, onep);
        float ub = sK * logf(tb + sqrtf(fmaxf(tb * tb - 1.f, 1e-7f)));
        ubv[tid - 32] = ub;
        bnv[tid - 32] = bn;
        g_u2[tid - 32] = ub * ub;     // ||u||^2 = ub^2 since u = ub * y/||y||
    }
    __syncthreads();
    if (tid < 128) {
        int j = tid & 63;
        if (tid < 64) g_uQ[j] = (j == 0) ? 0.f : ubv[0] * bq[j] / bnv[0];
        else          g_uK[j] = (j == 0) ? 0.f : ubv[1] * bk[j] / bnv[1];
    }
}

// ---------------- Kernel 3: fused main, 512 threads ----------------
extern "C" __global__ __launch_bounds__(512, 1)
void main_kernel(const float* __restrict__ H, const int* __restrict__ tidx,
                 const float* __restrict__ mask, const float* __restrict__ ain,
                 const float* __restrict__ cin, float* __restrict__ out) {
    extern __shared__ float smem[];
    float* tile = smem;                    // 16*1024
    float* qm   = tile + 16384;            // 16*1024
    float* km   = qm + 16384;              // 16*1024
    float* cQ   = km + 16384;              // 256
    float* cK   = cQ + 256;                // 256
    float* fQ   = cK + 256;                // 16
    float* fK   = fQ + 16;                 // 16
    float* uq   = fK + 16;                 // 64
    float* uk   = uq + 64;                 // 64
    int*   tmA  = (int*)(uk + 64);         // 136
    int*   tnA  = tmA + 136;               // 136
    float* maskS= (float*)(tnA + 136);     // 136
    float* sbuf = maskS + 136;             // 16*136
    float* zfac = sbuf + 16 * 136;         // 16*16 (lamb/ssum * 1/h0)
    float* wfac = zfac + 256;              // 16*16 (lamb/ssum)
    float* firsts = wfac + 256;            // 512: [qk*256 + samp*16 + tt] post-proj x0

    const int g = blockIdx.x;
    const int tid = threadIdx.x;
    const int lane = tid & 31, warp = tid >> 5;
    const float cval = __ldg(cin);
    const float aval = __ldg(ain);
    const float Kv = 1.f / cval;
    const float sK = sqrtf(Kv);
    const float onep = 1.f + 1e-7f;

    // ---- load constants + time index ----
    if (tid < 256) { cQ[tid] = g_coefQ[tid]; cK[tid] = g_coefK[tid]; }
    if (tid < 16)  { fQ[tid] = g_firstQ[tid]; fK[tid] = g_firstK[tid]; }
    if (tid < 64)  { uq[tid] = g_uQ[tid]; uk[tid] = g_uK[tid]; }
    bool is64 = (__ldg(&tidx[1]) == 0);   // int64 buffer read as int32 -> high word 0
    if (tid < 136) {
        int tm, tn;
        if (is64) { tm = tidx[2 * tid]; tn = tidx[272 + 2 * tid]; }
        else      { tm = tidx[tid];     tn = tidx[136 + tid]; }
        tmA[tid] = tm; tnA[tid] = tn; maskS[tid] = mask[tid];
    }
    // ---- load big_h tile: samples s*512+g ----
    for (int i = tid; i < 16 * 256; i += 512) {
        int s = i >> 8, c4 = i & 255;
        float4 v = reinterpret_cast<const float4*>(H + (size_t)(s * 512 + g) * 1024)[c4];
        reinterpret_cast<float4*>(tile + s * 1024)[c4] = v;
    }
    __syncthreads();

    // ---- phase 2: 16x16 mix -> q,k raw (packed f32x2) ----
    {
        const float2* t2 = reinterpret_cast<const float2*>(tile);
        float2* q2 = reinterpret_cast<float2*>(qm);
        float2* k2 = reinterpret_cast<float2*>(km);
        ull tv[16];
#pragma unroll
        for (int s = 0; s < 16; s++) {
            float2 v = t2[s * 512 + tid];
            tv[s] = pack2(v.x, v.y);
        }
#pragma unroll
        for (int r = 0; r < 16; r++) {
            const float4* cq4 = reinterpret_cast<const float4*>(cQ + r * 16);
            const float4* ck4 = reinterpret_cast<const float4*>(cK + r * 16);
            ull aq = 0ull, ak = 0ull;
#pragma unroll
            for (int s4 = 0; s4 < 4; s4++) {
                float4 cq = cq4[s4], ck = ck4[s4];
                aq = fma2(pack2(cq.x, cq.x), tv[s4 * 4 + 0], aq);
                aq = fma2(pack2(cq.y, cq.y), tv[s4 * 4 + 1], aq);
                aq = fma2(pack2(cq.z, cq.z), tv[s4 * 4 + 2], aq);
                aq = fma2(pack2(cq.w, cq.w), tv[s4 * 4 + 3], aq);
                ak = fma2(pack2(ck.x, ck.x), tv[s4 * 4 + 0], ak);
                ak = fma2(pack2(ck.y, ck.y), tv[s4 * 4 + 1], ak);
                ak = fma2(pack2(ck.z, ck.z), tv[s4 * 4 + 2], ak);
                ak = fma2(pack2(ck.w, ck.w), tv[s4 * 4 + 3], ak);
            }
            float qlo, qhi, klo, khi;
            unpack2(aq, qlo, qhi);
            unpack2(ak, klo, khi);
            if (g == 0 && tid == 0) { qlo = fQ[r]; klo = fK[r]; }  // expmap0 first column
            q2[r * 512 + tid] = make_float2(qlo, qhi);
            k2[r * 512 + tid] = make_float2(klo, khi);
        }
    }
    __syncthreads();

    // ---- phase 3: mobius_add(b) + proj, thread-per-row, closed-form reductions ----
    {
        float* X = (tid < 256) ? qm : km;
        const float4* U4 = reinterpret_cast<const float4*>((tid < 256) ? uq : uk);
        const float u2 = (tid < 256) ? g_u2[0] : g_u2[1];
        int rloc = tid & 255;
        float* row = X + (rloc >> 4) * 1024 + (rloc & 15) * 64;
        float4* row4 = reinterpret_cast<float4*>(row);

        float x0 = 0.f;
        float yn2a = 0.f, yn2b = 0.f, dua = 0.f, dub = 0.f;
#pragma unroll
        for (int jp = 0; jp < 16; jp++) {
            int p = (jp + lane) & 15;
            float4 xv = row4[p];
            float4 uv = U4[p];
            if (p == 0) x0 = xv.x;
            yn2a = fmaf(xv.x, xv.x, fmaf(xv.y, xv.y, yn2a));
            yn2b = fmaf(xv.z, xv.z, fmaf(xv.w, xv.w, yn2b));
            dua  = fmaf(xv.x, uv.x, fmaf(xv.y, uv.y, dua));
            dub  = fmaf(xv.z, uv.z, fmaf(xv.w, uv.w, dub));
        }
        float yn2 = (yn2a + yn2b) - x0 * x0;     // exclude dim0 (U[0]=0 so du is fine)
        float du  = dua + dub;

        float yn = fmaxf(sqrtf(fmaxf(yn2, 0.f)), 1e-15f);
        float alpha = du / (yn * sK);
        float fac = alpha * (sK - x0) / yn;
        float ux = du - fac * yn2;                       // x.(u - fac x) excl dim0
        float first = ux / fmaxf(x0, 1e-7f);
        float w2 = fmaf(fac * fac, yn2, fmaf(-2.f * fac, du, u2));  // |u-fac x|^2 excl dim0
        float md = fmaxf(w2 - first * first, 1e-7f);
        float nrm = fminf(sqrtf(md), 1e6f);
        float th = fmaxf(nrm / sK, 1e-15f);
        float ch = coshf(th);
        float shn = sinhf(th) / th;
        float A = fmaf(-shn, fac, ch);                   // rv = A*x + B*u
        float B = shn;
        float r2 = fmaf(A * A, yn2, fmaf(2.f * A * B, du, B * B * u2));
        float o0 = sqrtf(fmaxf(Kv + r2, 1e-7f));

#pragma unroll
        for (int jp = 0; jp < 16; jp++) {
            int p = (jp + lane) & 15;
            float4 xv = row4[p];
            float4 uv = U4[p];
            float4 rv;
            rv.x = fmaf(A, xv.x, B * uv.x);
            rv.y = fmaf(A, xv.y, B * uv.y);
            rv.z = fmaf(A, xv.z, B * uv.z);
            rv.w = fmaf(A, xv.w, B * uv.w);
            row4[p] = rv;
        }
        row[0] = o0;
        firsts[((tid < 256) ? 0 : 256) + rloc] = o0;
    }
    __syncthreads();

    // ---- phase 4: attention, warp per sample ----
    {
        const int sm = warp;
        const float* tsm = tile + sm * 1024;

        // lorenz factor + 1/x0: all 32 lanes (2 half-rows per tt), float4 rotated
        {
            int ttv = lane & 15, half = lane >> 4;
            const float4* bp4 = reinterpret_cast<const float4*>(tsm + ttv * 64 + half * 32);
            float h0c = 0.f, sva = 0.f, svb = 0.f;
#pragma unroll
            for (int j = 0; j < 8; j++) {
                int p = (j + ttv) & 7;
                float4 v = bp4[p];
                if (half == 0 && p == 0) h0c = v.x;
                sva = fmaf(v.x, v.x, fmaf(v.y, v.y, sva));
                svb = fmaf(v.z, v.z, fmaf(v.w, v.w, svb));
            }
            float sv = sva + svb;
            float h0v = __shfl_sync(0xffffffffu, h0c, ttv);
            sv += __shfl_xor_sync(0xffffffffu, sv, 16);
            float iv = 1.f / h0v;
            if (half == 0) {
                float svn = (sv - h0v * h0v) * iv * iv;
                wfac[sm * 16 + ttv] = rsqrtf(1.f - fminf(svn, 0.9f));  // lamb (pre-fold)
                zfac[sm * 16 + ttv] = iv;                              // 1/h0 (pre-fold)
            }
        }
        __syncwarp();

        // ---- dots: register-tiled 4x4 pair blocks + butterfly multi-reduce ----
        {
            const float2* q2 = reinterpret_cast<const float2*>(qm + sm * 1024);
            const float2* k2 = reinterpret_cast<const float2*>(km + sm * 1024);
            // bit-reverse of low 4 lane bits -> pair index owned by this lane
            const int brv = ((lane & 1) << 3) | ((lane & 2) << 1) | ((lane & 4) >> 1) | ((lane & 8) >> 3);
            const int pi = brv >> 2, pj = brv & 3;

            for (int bi = 0; bi < 4; bi++) {
                for (int bj = 0; bj <= bi; bj++) {
                    float2 qv[4], kv[4];
#pragma unroll
                    for (int i = 0; i < 4; i++) qv[i] = q2[(bi * 4 + i) * 32 + lane];
#pragma unroll
                    for (int j = 0; j < 4; j++) kv[j] = k2[(bj * 4 + j) * 32 + lane];
                    float acc[16];
#pragma unroll
                    for (int i = 0; i < 4; i++)
#pragma unroll
                        for (int j = 0; j < 4; j++)
                            acc[i * 4 + j] = fmaf(qv[i].x, kv[j].x, qv[i].y * kv[j].y);
                    // butterfly multi-reduce: 16 values over 32 lanes
#pragma unroll
                    for (int step = 0; step < 4; step++) {
                        const int mm = 1 << step;
                        const int h = 8 >> step;
                        const bool hi = (lane & mm) != 0;
#pragma unroll
                        for (int i = 0; i < h; i++) {
                            float sent = hi ? acc[i] : acc[i + h];
                            float recv = __shfl_xor_sync(0xffffffffu, sent, mm);
                            acc[i] = (hi ? acc[i + h] : acc[i]) + recv;
                        }
                    }
                    float S = acc[0] + __shfl_xor_sync(0xffffffffu, acc[0], 16);
                    int mt = bi * 4 + pi, nt = bj * 4 + pj;
                    if (lane < 16 && nt <= mt) {
                        int e = ((mt * (mt + 1)) >> 1) + nt;
                        float q0 = firsts[sm * 16 + mt];
                        float k0 = firsts[256 + sm * 16 + nt];
                        float mdot = S - 2.f * q0 * k0;
                        float thv = fmaxf(-mdot * cval, onep);
                        float ar = __logf(thv + sqrtf(fmaxf(thv * thv - 1.f, 1e-7f)));
                        float sq = fminf(Kv * ar * ar, 50.f);
                        sbuf[sm * 136 + e] = __expf(fmaf(-aval, sq, maskS[e] - cval));
                    }
                }
            }
        }
        __syncwarp();

        // ---- ssum per m (static triangular) + fold factors ----
        if (lane < 16) {
            const float* sb = sbuf + sm * 136 + ((lane * (lane + 1)) >> 1);
            float acc = 0.f;
            for (int j = 0; j <= lane; j++) acc += sb[j];
            float f = wfac[sm * 16 + lane] / acc;    // lamb / ssum
            wfac[sm * 16 + lane] = f;
            zfac[sm * 16 + lane] = f * zfac[sm * 16 + lane];
        }
        __syncwarp();

        // ---- scatter: fully unrolled triangular, v rows in registers ----
        {
            const float2* tsm2 = reinterpret_cast<const float2*>(tsm);
            float2 v16[16];
#pragma unroll
            for (int n = 0; n < 16; n++) v16[n] = tsm2[n * 32 + lane];
            const float* sb = sbuf + sm * 136;
            const float* zf = zfac + sm * 16;
            const float* wf = wfac + sm * 16;
            const size_t obase = (size_t)(sm * 512 + g) * 1024;
#pragma unroll
            for (int m = 0; m < 16; m++) {
                float azx = 0.f, azy = 0.f, wacc = 0.f;
#pragma unroll
                for (int n = 0; n <= m; n++) {
                    float se = sb[((m * (m + 1)) >> 1) + n];
                    float fz = se * zf[n];
                    wacc = fmaf(se, wf[n], wacc);
                    azx = fmaf(fz, v16[n].x, azx);
                    azy = fmaf(fz, v16[n].y, azy);
                }
                float iw = __fdividef(1.f, wacc);
                float ox = azx * iw, oy = azy * iw;
                float contrib = (lane == 0) ? oy * oy : fmaf(ox, ox, oy * oy);
                float s2 = wreduce(contrib);
                float inv = rsqrtf(1.f - fminf(s2, 0.999f));
                float2 ov = make_float2(ox * inv, oy * inv);
                if (lane == 0) ov.x = inv;   // out[0] = lorenz of result
                reinterpret_cast<float2*>(out + obase + (size_t)m * 64)[lane] = ov;
            }
        }
    }
}

// ---------------- launch ----------------
extern "C" void kernel_launch(void* const* d_in, const int* in_sizes, int n_in,
                              void* d_out, int out_size) {
    (void)in_sizes; (void)n_in; (void)out_size;
    const float* H    = (const float*)d_in[0];
    const int*   tidx = (const int*)d_in[1];
    const float* mask = (const float*)d_in[2];
    const float* wq   = (const float*)d_in[3];
    const float* wk   = (const float*)d_in[4];
    const float* bq   = (const float*)d_in[5];
    const float* bk   = (const float*)d_in[6];
    const float* a    = (const float*)d_in[7];
    const float* c    = (const float*)d_in[8];
    float* out = (float*)d_out;

    const int MAIN_FLOATS = 3 * 16384 + 256 + 256 + 16 + 16 + 64 + 64
                            + 136 + 136 + 136 + 16 * 136 + 256 + 256 + 512;
    const int MAIN_SMEM = MAIN_FLOATS * 4;   // ~209KB

    cudaFuncSetAttribute(main_kernel, cudaFuncAttributeMaxDynamicSharedMemorySize, MAIN_SMEM);

    gram_kernel<<<GNTILE, 320>>>(H);
    reduce_kernel<<<NPAIR, 256>>>();
    finalize_kernel<<<1, 256>>>(H, wq, wk, bq, bk, c);
    main_kernel<<<512, 512, MAIN_SMEM>>>(H, tidx, mask, a, c, out);
}